// round 15
// baseline (speedup 1.0000x reference)
#include <cuda_runtime.h>
#include <cuda_fp16.h>
#include <math.h>
#include <stdint.h>

#define D_MODEL 1024
#define N_HEADS 16
#define D_HEAD 64
#define D_FF 4096
#define SEQ 2048
#define BATCH 2
#define TOKENS (BATCH * SEQ)
#define QKV_N (3 * D_MODEL)
#define BH (BATCH * N_HEADS)

typedef __half hf;

// ---------------- scratch ----------------
__device__ hf g_WqkvT[QKV_N * D_MODEL];
__device__ hf g_WoT[D_MODEL * D_MODEL];
__device__ hf g_W1T[D_FF * D_MODEL];
__device__ hf g_W2T[D_MODEL * D_FF];
__device__ hf g_xn[TOKENS * D_MODEL];
// head-major QKV: [bh][s][64]
__device__ hf g_q[BH * SEQ * D_HEAD];
__device__ hf g_k[BH * SEQ * D_HEAD];
__device__ hf g_v[BH * SEQ * D_HEAD];
__device__ hf g_at[TOKENS * D_MODEL];
__device__ float g_hidden[TOKENS * D_MODEL];
__device__ hf g_hn[TOKENS * D_MODEL];
__device__ hf g_ff[(size_t)TOKENS * D_FF];
__device__ int g_ln_ctr[32];

__device__ __forceinline__ uint32_t smem_to_u32(const void* p) {
    uint32_t a;
    asm("{ .reg .u64 t; cvta.to.shared.u64 t, %1; cvt.u32.u64 %0, t; }"
        : "=r"(a) : "l"(p));
    return a;
}
__device__ __forceinline__ void cp_async16(uint32_t smem, const void* gmem) {
    asm volatile("cp.async.cg.shared.global [%0], [%1], 16;" :: "r"(smem), "l"(gmem));
}
__device__ __forceinline__ void cp_commit() { asm volatile("cp.async.commit_group;"); }
template <int N>
__device__ __forceinline__ void cp_wait() { asm volatile("cp.async.wait_group %0;" :: "n"(N)); }

__device__ __forceinline__ void ldm_x4(uint32_t& r0, uint32_t& r1, uint32_t& r2, uint32_t& r3,
                                       uint32_t addr) {
    asm volatile("ldmatrix.sync.aligned.m8n8.x4.shared.b16 {%0,%1,%2,%3}, [%4];"
                 : "=r"(r0), "=r"(r1), "=r"(r2), "=r"(r3) : "r"(addr));
}
__device__ __forceinline__ void ldm_x4_t(uint32_t& r0, uint32_t& r1, uint32_t& r2, uint32_t& r3,
                                         uint32_t addr) {
    asm volatile("ldmatrix.sync.aligned.m8n8.x4.trans.shared.b16 {%0,%1,%2,%3}, [%4];"
                 : "=r"(r0), "=r"(r1), "=r"(r2), "=r"(r3) : "r"(addr));
}
__device__ __forceinline__ void mma_f16(float& c0, float& c1, float& c2, float& c3,
                                        uint32_t a0, uint32_t a1, uint32_t a2, uint32_t a3,
                                        uint32_t b0, uint32_t b1) {
    asm volatile(
        "mma.sync.aligned.m16n8k16.row.col.f32.f16.f16.f32 "
        "{%0,%1,%2,%3}, {%4,%5,%6,%7}, {%8,%9}, {%0,%1,%2,%3};"
        : "+f"(c0), "+f"(c1), "+f"(c2), "+f"(c3)
        : "r"(a0), "r"(a1), "r"(a2), "r"(a3), "r"(b0), "r"(b1));
}

__device__ __forceinline__ float gelu_exact(float v) {
    return 0.5f * v * (1.0f + erff(v * 0.70710678118654752440f));
}

// ---- packed f32x2 helpers (sm_100+ base PTX) ----
__device__ __forceinline__ uint64_t pk2(float a, float b) {
    uint64_t r; asm("mov.b64 %0, {%1, %2};" : "=l"(r) : "f"(a), "f"(b)); return r;
}
__device__ __forceinline__ void upk2(uint64_t v, float& a, float& b) {
    asm("mov.b64 {%0, %1}, %2;" : "=f"(a), "=f"(b) : "l"(v));
}
__device__ __forceinline__ uint64_t add2_(uint64_t a, uint64_t b) {
    uint64_t r; asm("add.rn.f32x2 %0, %1, %2;" : "=l"(r) : "l"(a), "l"(b)); return r;
}
__device__ __forceinline__ uint64_t fma2_(uint64_t a, uint64_t b, uint64_t c) {
    uint64_t r; asm("fma.rn.f32x2 %0, %1, %2, %3;" : "=l"(r) : "l"(a), "l"(b), "l"(c)); return r;
}
// exp2 of two values at once, pure FMA/ALU pipes (no MUFU). inputs expected <= 0.
__device__ __forceinline__ void exp2_pair(float& x0, float& x1) {
    float t0 = fmaxf(x0, -126.0f), t1 = fmaxf(x1, -126.0f);
    uint64_t t = pk2(t0, t1);
    uint64_t fn = add2_(t, pk2(12582912.0f, 12582912.0f));
    float fn0, fn1; upk2(fn, fn0, fn1);
    int n0 = __float_as_int(fn0) - 0x4B400000;
    int n1 = __float_as_int(fn1) - 0x4B400000;
    uint64_t fm = add2_(fn, pk2(-12582912.0f, -12582912.0f));
    uint64_t f = fma2_(fm, pk2(-1.0f, -1.0f), t);  // f = t - (fn - magic)
    uint64_t p = pk2(0.0013333558f, 0.0013333558f);
    p = fma2_(p, f, pk2(0.0096181291f, 0.0096181291f));
    p = fma2_(p, f, pk2(0.0555041087f, 0.0555041087f));
    p = fma2_(p, f, pk2(0.2402265070f, 0.2402265070f));
    p = fma2_(p, f, pk2(0.6931471806f, 0.6931471806f));
    p = fma2_(p, f, pk2(1.0f, 1.0f));
    float p0, p1; upk2(p, p0, p1);
    x0 = __int_as_float(__float_as_int(p0) + (n0 << 23));
    x1 = __int_as_float(__float_as_int(p1) + (n1 << 23));
}

__device__ __forceinline__ uint32_t pack_h(hf a, hf b) {
    __half2 p = __halves2half2(a, b);
    return *(uint32_t*)&p;
}
__device__ __forceinline__ uint32_t pack_hf(float a, float b) {
    return pack_h(__float2half_rn(a), __float2half_rn(b));
}

#define QSCALE 0.18033688011f  // 0.125 * log2(e)

// ---------------- prep: Wqkv transpose + LN1 + zero LN counters ----------------
// blocks [0,3072)    : Wqkv transpose (32x32 tiles)
// blocks [3072,7168) : LN1 rows
__global__ __launch_bounds__(256) void prep_k(
    const float* __restrict__ Wq, const float* __restrict__ Wk, const float* __restrict__ Wv,
    const float* __restrict__ x, const float* __restrict__ g, const float* __restrict__ b,
    hf* __restrict__ dQkv, hf* __restrict__ oXn) {
    __shared__ float t[32][33];
    __shared__ float red[2][8];
    const int bid = blockIdx.x;
    const int tid = threadIdx.x;

    if (bid == 0 && tid < 32) g_ln_ctr[tid] = 0;

    if (bid < 3072) {
        int kt = bid & 31, nt = bid >> 5;
        int k0 = kt * 32, n0 = nt * 32;
        int w = n0 >> 10, h = (n0 >> 6) & 15;
        const float* W = (w == 0) ? Wq : (w == 1) ? Wk : Wv;
        const float* src = W + (size_t)h * D_MODEL * D_HEAD;
        int srcCol = n0 & 63;
        const int tx = tid & 31, ty = tid >> 5;
#pragma unroll
        for (int i = 0; i < 4; i++)
            t[ty + i * 8][tx] = src[(size_t)(k0 + ty + i * 8) * 64 + srcCol + tx];
        __syncthreads();
#pragma unroll
        for (int i = 0; i < 4; i++) {
            size_t o = (size_t)(n0 + ty + i * 8) * D_MODEL + k0 + tx;
            dQkv[o] = __float2half_rn(t[tx][ty + i * 8]);
        }
    } else {
        int row = bid - 3072;
        const float4* xr = (const float4*)(x + (size_t)row * D_MODEL);
        float4 v = xr[tid];
        float s = v.x + v.y + v.z + v.w;
        float ss = v.x * v.x + v.y * v.y + v.z * v.z + v.w * v.w;
#pragma unroll
        for (int of = 16; of > 0; of >>= 1) {
            s += __shfl_xor_sync(0xffffffffu, s, of);
            ss += __shfl_xor_sync(0xffffffffu, ss, of);
        }
        int w = tid >> 5, l = tid & 31;
        if (l == 0) { red[0][w] = s; red[1][w] = ss; }
        __syncthreads();
        if (tid < 32) {
            s = (l < 8) ? red[0][l] : 0.f;
            ss = (l < 8) ? red[1][l] : 0.f;
#pragma unroll
            for (int of = 4; of > 0; of >>= 1) {
                s += __shfl_xor_sync(0xffffffffu, s, of);
                ss += __shfl_xor_sync(0xffffffffu, ss, of);
            }
            if (l == 0) { red[0][0] = s; red[1][0] = ss; }
        }
        __syncthreads();
        float mu = red[0][0] * (1.0f / D_MODEL);
        float var = red[1][0] * (1.0f / D_MODEL) - mu * mu;
        float r = rsqrtf(var + 1e-5f);
        float4 gv = ((const float4*)g)[tid];
        float4 bv = ((const float4*)b)[tid];
        float o0 = (v.x - mu) * r * gv.x + bv.x;
        float o1 = (v.y - mu) * r * gv.y + bv.y;
        float o2 = (v.z - mu) * r * gv.z + bv.z;
        float o3 = (v.w - mu) * r * gv.w + bv.w;
        size_t base = (size_t)row * D_MODEL + tid * 4;
        *(uint32_t*)(oXn + base) = pack_hf(o0, o1);
        *(uint32_t*)(oXn + base + 2) = pack_hf(o2, o3);
    }
}

// ---------------- fp16 HMMA GEMM, 1 pass, 128x128x32 tiles ----------------
// EPI: 1 bias+residual fp32 C; 2 bias+GELU fp16; 3 QKV head-major (Q scaled)
// LNF: fused LN2 — last finishing column-block per M-tile computes LN of its 128 rows
#define GSTAGES 3
#define STAGE_BYTES 16384

template <int EPI, int LNF>
__global__ __launch_bounds__(256, 2) void gemm_mma(
    const hf* __restrict__ A, const hf* __restrict__ B,
    int K, int N,
    float* __restrict__ C, hf* __restrict__ Ch,
    const float* __restrict__ bias, const float* __restrict__ res,
    hf* __restrict__ Qd, hf* __restrict__ Kd, hf* __restrict__ Vd,
    const float* __restrict__ lng, const float* __restrict__ lnb,
    hf* __restrict__ Hn) {
    extern __shared__ char smem[];
    const uint32_t sb = smem_to_u32(smem);
    const int tid = threadIdx.x;
    const int lane = tid & 31;
    const int warp = tid >> 5;
    const int warpM = warp & 3, warpN = warp >> 2;
    const int bn = blockIdx.x * 128, bm = blockIdx.y * 128;

    const size_t rstrideB = (size_t)K * 2;
    const char* gA = (const char*)A + (size_t)bm * K * 2;
    const char* gB = (const char*)B + (size_t)bn * K * 2;

    const int NK = K >> 5;

    auto issue_chunk = [&](int c) {
        const uint32_t stg = sb + (uint32_t)(c % GSTAGES) * STAGE_BYTES;
        const size_t goff = (size_t)c * 64;
#pragma unroll
        for (int j = 0; j < 4; j++) {
            int id = tid + j * 256;
            int arr = id >> 9;
            int row = (id >> 2) & 127;
            int seg = id & 3;
            const char* src = (arr ? gB : gA) + goff + (size_t)row * rstrideB + seg * 16;
            uint32_t dst = stg + (uint32_t)arr * 8192 + (uint32_t)row * 64 +
                           ((uint32_t)(seg ^ ((row >> 1) & 3)) << 4);
            cp_async16(dst, src);
        }
    };

    const int aRow = warpM * 32 + (lane & 15);
    const int aKh = lane >> 4;
    const uint32_t aSw = (aRow >> 1) & 3;
    const uint32_t aRowB = (uint32_t)aRow * 64;
    const int bRowBase = warpN * 64 + (lane & 15);
    const int bKh = lane >> 4;
    const uint32_t bSw = (bRowBase >> 1) & 3;
    const uint32_t bRowB = (uint32_t)bRowBase * 64;

    float acc[2][8][4];
#pragma unroll
    for (int i = 0; i < 2; i++)
#pragma unroll
        for (int j = 0; j < 8; j++)
#pragma unroll
            for (int q = 0; q < 4; q++) acc[i][j][q] = 0.f;

#pragma unroll
    for (int s = 0; s < GSTAGES - 1; s++) { issue_chunk(s); cp_commit(); }

    for (int c = 0; c < NK; c++) {
        cp_wait<GSTAGES - 2>();
        __syncthreads();
        const uint32_t stg = sb + (uint32_t)(c % GSTAGES) * STAGE_BYTES;
#pragma unroll
        for (int k16 = 0; k16 < 2; k16++) {
            const uint32_t aSeg = ((uint32_t)(k16 * 2 + aKh) ^ aSw) << 4;
            const uint32_t bSeg = ((uint32_t)(k16 * 2 + bKh) ^ bSw) << 4;
            uint32_t ah[2][4], bh[4][4];
#pragma unroll
            for (int i = 0; i < 2; i++)
                ldm_x4(ah[i][0], ah[i][1], ah[i][2], ah[i][3],
                       stg + aRowB + (uint32_t)i * 16 * 64 + aSeg);
#pragma unroll
            for (int t = 0; t < 4; t++)
                ldm_x4(bh[t][0], bh[t][1], bh[t][2], bh[t][3],
                       stg + 8192 + bRowB + (uint32_t)t * 16 * 64 + bSeg);
#pragma unroll
            for (int i = 0; i < 2; i++)
#pragma unroll
                for (int t = 0; t < 4; t++) {
                    float* c0 = acc[i][2 * t];
                    float* c1 = acc[i][2 * t + 1];
                    mma_f16(c0[0], c0[1], c0[2], c0[3],
                            ah[i][0], ah[i][1], ah[i][2], ah[i][3], bh[t][0], bh[t][2]);
                    mma_f16(c1[0], c1[1], c1[2], c1[3],
                            ah[i][0], ah[i][1], ah[i][2], ah[i][3], bh[t][1], bh[t][3]);
                }
        }
        __syncthreads();
        if (c + GSTAGES - 1 < NK) issue_chunk(c + GSTAGES - 1);
        cp_commit();
    }

    const int gRow = lane >> 2;
    const int gCol = (lane & 3) * 2;
#pragma unroll
    for (int i = 0; i < 2; i++) {
#pragma unroll
        for (int j = 0; j < 8; j++) {
            int row = bm + warpM * 32 + i * 16 + gRow;
            int col = bn + warpN * 64 + j * 8 + gCol;
#pragma unroll
            for (int half = 0; half < 2; half++) {
                int r = row + half * 8;
                float v0 = acc[i][j][half * 2 + 0];
                float v1 = acc[i][j][half * 2 + 1];
                if (EPI == 1 || EPI == 2) {
                    float2 bb = *(const float2*)(bias + col);
                    v0 += bb.x; v1 += bb.y;
                }
                if (EPI == 1) {
                    float2 rv = *(const float2*)(res + (size_t)r * N + col);
                    v0 += rv.x; v1 += rv.y;
                    *(float2*)(C + (size_t)r * N + col) = make_float2(v0, v1);
                } else if (EPI == 2) {
                    v0 = gelu_exact(v0); v1 = gelu_exact(v1);
                    *(uint32_t*)(Ch + (size_t)r * N + col) = pack_hf(v0, v1);
                } else if (EPI == 3) {
                    int which = col >> 10;
                    int h = (col >> 6) & 15;
                    int e = col & 63;
                    int bb = r >> 11, s = r & 2047;
                    size_t o = (((size_t)(bb * 16 + h)) * SEQ + s) * D_HEAD + e;
                    if (which == 0) { v0 *= QSCALE; v1 *= QSCALE; }
                    hf* dst = (which == 0) ? Qd : (which == 1) ? Kd : Vd;
                    *(uint32_t*)(dst + o) = pack_hf(v0, v1);
                }
            }
        }
    }

    if (LNF) {
        // fused LN2: last column-block for this M-tile normalizes its 128 rows
        __threadfence();
        __syncthreads();
        __shared__ int lastFlag;
        if (tid == 0)
            lastFlag = (atomicAdd(&g_ln_ctr[blockIdx.y], 1) == (int)gridDim.x - 1);
        __syncthreads();
        if (!lastFlag) return;
        __threadfence();
        float* sg = (float*)smem;
        float* sb2 = sg + 1024;
        for (int i = tid; i < 1024; i += 256) { sg[i] = lng[i]; sb2[i] = lnb[i]; }
        __syncthreads();
        const int w = tid >> 5, l = tid & 31;
#pragma unroll 1
        for (int rr = 0; rr < 16; rr++) {
            int row = bm + w * 16 + rr;
            const float4* xr = (const float4*)(C + (size_t)row * D_MODEL);
            float4 vv[8];
            float s = 0.f, ss = 0.f;
#pragma unroll
            for (int i = 0; i < 8; i++) {
                float4 v = xr[l + 32 * i];
                vv[i] = v;
                s += v.x + v.y + v.z + v.w;
                ss += v.x * v.x + v.y * v.y + v.z * v.z + v.w * v.w;
            }
#pragma unroll
            for (int of = 16; of > 0; of >>= 1) {
                s += __shfl_xor_sync(0xffffffffu, s, of);
                ss += __shfl_xor_sync(0xffffffffu, ss, of);
            }
            float mu = s * (1.0f / D_MODEL);
            float var = ss * (1.0f / D_MODEL) - mu * mu;
            float rs = rsqrtf(var + 1e-5f);
            hf* dst = Hn + (size_t)row * D_MODEL;
#pragma unroll
            for (int i = 0; i < 8; i++) {
                int c4 = (l + 32 * i) * 4;
                float o0 = (vv[i].x - mu) * rs * sg[c4 + 0] + sb2[c4 + 0];
                float o1 = (vv[i].y - mu) * rs * sg[c4 + 1] + sb2[c4 + 1];
                float o2 = (vv[i].z - mu) * rs * sg[c4 + 2] + sb2[c4 + 2];
                float o3 = (vv[i].w - mu) * rs * sg[c4 + 3] + sb2[c4 + 3];
                *(uint32_t*)(dst + c4) = pack_hf(o0, o1);
                *(uint32_t*)(dst + c4 + 2) = pack_hf(o2, o3);
            }
        }
    }
}

// ---------------- fp16 HMMA flash attention + absorbed weight transposes ------------
#define ATT_SMEM (16384 + 2 * 16384)
#define TRB 288  // transpose blocks = 16 * 18

__global__ __launch_bounds__(256, 2) void attn_mma(
    const hf* __restrict__ q_g, const hf* __restrict__ k_g, const hf* __restrict__ v_g,
    hf* __restrict__ oh,
    const float* __restrict__ Wo, const float* __restrict__ W1, const float* __restrict__ W2,
    hf* __restrict__ dWo, hf* __restrict__ dW1, hf* __restrict__ dW2) {
    extern __shared__ char smem[];
    const int tid = threadIdx.x;

    if (blockIdx.y >= BH) {
        float (*t)[33] = (float(*)[33])smem;
        const int tb = (blockIdx.y - BH) * 16 + blockIdx.x;
        const int tx = tid & 31, ty = tid >> 5;
#pragma unroll 1
        for (int it = 0; it < 32; it++) {
            int tile = tb + it * TRB;
            const float* src;
            hf* dst;
            int k0, n0, srcStride, Kd;
            if (tile < 1024) {
                k0 = (tile & 31) * 32; n0 = (tile >> 5) * 32;
                src = Wo; srcStride = D_MODEL; dst = dWo; Kd = D_MODEL;
            } else if (tile < 5120) {
                int tt = tile - 1024;
                k0 = (tt & 31) * 32; n0 = (tt >> 5) * 32;
                src = W1; srcStride = D_FF; dst = dW1; Kd = D_MODEL;
            } else {
                int tt = tile - 5120;
                k0 = (tt & 127) * 32; n0 = (tt >> 7) * 32;
                src = W2; srcStride = D_MODEL; dst = dW2; Kd = D_FF;
            }
#pragma unroll
            for (int i = 0; i < 4; i++)
                t[ty + i * 8][tx] = src[(size_t)(k0 + ty + i * 8) * srcStride + n0 + tx];
            __syncthreads();
#pragma unroll
            for (int i = 0; i < 4; i++) {
                size_t o = (size_t)(n0 + ty + i * 8) * Kd + k0 + tx;
                dst[o] = __float2half_rn(t[tx][ty + i * 8]);
            }
            __syncthreads();
        }
        return;
    }

    const uint32_t sb = smem_to_u32(smem);
    const int lane = tid & 31;
    const int warp = tid >> 5;
    const int bh = blockIdx.y;
    const int q0 = blockIdx.x * 128;

    const char* qb = (const char*)(q_g + ((size_t)bh * SEQ + q0) * D_HEAD);
    const char* kb = (const char*)(k_g + (size_t)bh * SEQ * D_HEAD);
    const char* vb = (const char*)(v_g + (size_t)bh * SEQ * D_HEAD);

    {
#pragma unroll
        for (int j = 0; j < 4; j++) {
            int id = tid + j * 256;
            int row = (id >> 3) & 127, seg = id & 7;
            uint32_t dst = sb + (uint32_t)row * 128 + ((uint32_t)(seg ^ (row & 7)) << 4);
            cp_async16(dst, qb + (size_t)row * 128 + seg * 16);
        }
    }
    auto issue_kv = [&](int kt) {
        const uint32_t stg = sb + 16384 + (uint32_t)(kt & 1) * 16384;
        const size_t gof = (size_t)kt * 64 * 128;
#pragma unroll
        for (int j = 0; j < 4; j++) {
            int id = tid + j * 256;
            int arr = id >> 9, row = (id >> 3) & 63, seg = id & 7;
            const char* src = ((arr == 0) ? kb : vb) + gof + (size_t)row * 128 + seg * 16;
            uint32_t dst = stg + (uint32_t)arr * 8192 + (uint32_t)row * 128 +
                           ((uint32_t)(seg ^ (row & 7)) << 4);
            cp_async16(dst, src);
        }
    };

    issue_kv(0);
    cp_commit();
    issue_kv(1);
    cp_commit();

    float accO[8][4];
#pragma unroll
    for (int t = 0; t < 8; t++)
#pragma unroll
        for (int q = 0; q < 4; q++) accO[t][q] = 0.f;
    float m0 = -1e30f, m1 = -1e30f, l0 = 0.f, l1 = 0.f;

    uint32_t qf[4][4];
    const int qRow = warp * 16 + (lane & 15);
    const uint32_t qSw = (uint32_t)(qRow & 7);
    const uint32_t qRowB = (uint32_t)qRow * 128;

    const int NT = SEQ / 64;
    for (int kt = 0; kt < NT; kt++) {
        cp_wait<1>();
        __syncthreads();
        if (kt == 0) {
#pragma unroll
            for (int ks = 0; ks < 4; ks++) {
                uint32_t seg = ((uint32_t)(ks * 2 + (lane >> 4)) ^ qSw) << 4;
                ldm_x4(qf[ks][0], qf[ks][1], qf[ks][2], qf[ks][3], sb + qRowB + seg);
            }
        }
        const uint32_t stg = sb + 16384 + (uint32_t)(kt & 1) * 16384;

        float S[8][4];
#pragma unroll
        for (int t = 0; t < 8; t++)
#pragma unroll
            for (int q = 0; q < 4; q++) S[t][q] = 0.f;

        const int nRow = lane & 15;
        const int kh4 = lane >> 4;
#pragma unroll
        for (int ks = 0; ks < 4; ks++) {
            uint32_t kh[4][4];
#pragma unroll
            for (int g = 0; g < 4; g++) {
                int row = g * 16 + nRow;
                uint32_t seg = ((uint32_t)(ks * 2 + kh4) ^ (uint32_t)(row & 7)) << 4;
                ldm_x4(kh[g][0], kh[g][1], kh[g][2], kh[g][3],
                       stg + (uint32_t)row * 128 + seg);
            }
#pragma unroll
            for (int g = 0; g < 4; g++) {
                float* c0 = S[2 * g];
                float* c1 = S[2 * g + 1];
                mma_f16(c0[0], c0[1], c0[2], c0[3],
                        qf[ks][0], qf[ks][1], qf[ks][2], qf[ks][3], kh[g][0], kh[g][2]);
                mma_f16(c1[0], c1[1], c1[2], c1[3],
                        qf[ks][0], qf[ks][1], qf[ks][2], qf[ks][3], kh[g][1], kh[g][3]);
            }
        }

        float mx0 = S[0][0], mx1 = S[0][2];
#pragma unroll
        for (int t = 0; t < 8; t++) {
            mx0 = fmaxf(mx0, fmaxf(S[t][0], S[t][1]));
            mx1 = fmaxf(mx1, fmaxf(S[t][2], S[t][3]));
        }
        mx0 = fmaxf(mx0, __shfl_xor_sync(0xffffffffu, mx0, 1));
        mx0 = fmaxf(mx0, __shfl_xor_sync(0xffffffffu, mx0, 2));
        mx1 = fmaxf(mx1, __shfl_xor_sync(0xffffffffu, mx1, 1));
        mx1 = fmaxf(mx1, __shfl_xor_sync(0xffffffffu, mx1, 2));
        float mn0 = fmaxf(m0, mx0), mn1 = fmaxf(m1, mx1);
        float cr0 = m0 - mn0, cr1 = m1 - mn1;
        exp2_pair(cr0, cr1);
        m0 = mn0; m1 = mn1;
        float sum0 = 0.f, sum1 = 0.f;
#pragma unroll
        for (int t = 0; t < 8; t++) {
            float a0 = S[t][0] - mn0, a1 = S[t][1] - mn0;
            float b0 = S[t][2] - mn1, b1 = S[t][3] - mn1;
            exp2_pair(a0, a1);
            exp2_pair(b0, b1);
            S[t][0] = a0; S[t][1] = a1; S[t][2] = b0; S[t][3] = b1;
            sum0 += a0 + a1;
            sum1 += b0 + b1;
        }
        sum0 += __shfl_xor_sync(0xffffffffu, sum0, 1);
        sum0 += __shfl_xor_sync(0xffffffffu, sum0, 2);
        sum1 += __shfl_xor_sync(0xffffffffu, sum1, 1);
        sum1 += __shfl_xor_sync(0xffffffffu, sum1, 2);
        l0 = l0 * cr0 + sum0;
        l1 = l1 * cr1 + sum1;
#pragma unroll
        for (int t = 0; t < 8; t++) {
            accO[t][0] *= cr0; accO[t][1] *= cr0;
            accO[t][2] *= cr1; accO[t][3] *= cr1;
        }

        const int vRow16 = lane & 15;
        const int vEh = lane >> 4;
#pragma unroll
        for (int ks = 0; ks < 4; ks++) {
            uint32_t pa[4];
            pa[0] = pack_hf(S[2 * ks][0], S[2 * ks][1]);
            pa[1] = pack_hf(S[2 * ks][2], S[2 * ks][3]);
            pa[2] = pack_hf(S[2 * ks + 1][0], S[2 * ks + 1][1]);
            pa[3] = pack_hf(S[2 * ks + 1][2], S[2 * ks + 1][3]);

            uint32_t vh[4][4];
#pragma unroll
            for (int g = 0; g < 4; g++) {
                int row = ks * 16 + vRow16;
                uint32_t seg = ((uint32_t)(g * 2 + vEh) ^ (uint32_t)(row & 7)) << 4;
                ldm_x4_t(vh[g][0], vh[g][1], vh[g][2], vh[g][3],
                         stg + 8192 + (uint32_t)row * 128 + seg);
            }
#pragma unroll
            for (int g = 0; g < 4; g++) {
                float* c0 = accO[2 * g];
                float* c1 = accO[2 * g + 1];
                mma_f16(c0[0], c0[1], c0[2], c0[3],
                        pa[0], pa[1], pa[2], pa[3], vh[g][0], vh[g][1]);
                mma_f16(c1[0], c1[1], c1[2], c1[3],
                        pa[0], pa[1], pa[2], pa[3], vh[g][2], vh[g][3]);
            }
        }
        __syncthreads();
        if (kt + 2 < NT) issue_kv(kt + 2);
        cp_commit();
    }

    float inv0 = 1.0f / l0, inv1 = 1.0f / l1;
    const int b = bh >> 4, h = bh & 15;
    const int r1 = q0 + warp * 16 + (lane >> 2);
    const int r2 = r1 + 8;
    size_t t1 = ((size_t)(b * SEQ) + r1) * D_MODEL + h * D_HEAD;
    size_t t2 = ((size_t)(b * SEQ) + r2) * D_MODEL + h * D_HEAD;
#pragma unroll
    for (int t = 0; t < 8; t++) {
        int e = t * 8 + (lane & 3) * 2;
        *(uint32_t*)(oh + t1 + e) = pack_hf(accO[t][0] * inv0, accO[t][1] * inv0);
        *(uint32_t*)(oh + t2 + e) = pack_hf(accO[t][2] * inv1, accO[t][3] * inv1);
    }
}

// ---------------- launch ----------------
extern "C" void kernel_launch(void* const* d_in, const int* in_sizes, int n_in,
                              void* d_out, int out_size) {
    const float* x    = (const float*)d_in[0];
    const float* Wq   = (const float*)d_in[1];
    const float* Wk   = (const float*)d_in[2];
    const float* Wv   = (const float*)d_in[3];
    const float* Wo   = (const float*)d_in[4];
    const float* bo   = (const float*)d_in[5];
    const float* ln1g = (const float*)d_in[6];
    const float* ln1b = (const float*)d_in[7];
    const float* ln2g = (const float*)d_in[8];
    const float* ln2b = (const float*)d_in[9];
    const float* W1   = (const float*)d_in[10];
    const float* b1   = (const float*)d_in[11];
    const float* W2   = (const float*)d_in[12];
    const float* b2   = (const float*)d_in[13];
    float* out = (float*)d_out;

    hf *pWqkv, *pWo, *pW1, *pW2, *pXn, *pAt, *pHn, *pFf, *pQ, *pK, *pV;
    float* pHid;
    cudaGetSymbolAddress((void**)&pWqkv, g_WqkvT);
    cudaGetSymbolAddress((void**)&pWo, g_WoT);
    cudaGetSymbolAddress((void**)&pW1, g_W1T);
    cudaGetSymbolAddress((void**)&pW2, g_W2T);
    cudaGetSymbolAddress((void**)&pXn, g_xn);
    cudaGetSymbolAddress((void**)&pAt, g_at);
    cudaGetSymbolAddress((void**)&pHn, g_hn);
    cudaGetSymbolAddress((void**)&pFf, g_ff);
    cudaGetSymbolAddress((void**)&pQ, g_q);
    cudaGetSymbolAddress((void**)&pK, g_k);
    cudaGetSymbolAddress((void**)&pV, g_v);
    cudaGetSymbolAddress((void**)&pHid, g_hidden);

    const int GEMM_SMEM = GSTAGES * STAGE_BYTES;  // 49152
    cudaFuncSetAttribute((gemm_mma<1, 0>), cudaFuncAttributeMaxDynamicSharedMemorySize, GEMM_SMEM);
    cudaFuncSetAttribute((gemm_mma<1, 1>), cudaFuncAttributeMaxDynamicSharedMemorySize, GEMM_SMEM);
    cudaFuncSetAttribute((gemm_mma<2, 0>), cudaFuncAttributeMaxDynamicSharedMemorySize, GEMM_SMEM);
    cudaFuncSetAttribute((gemm_mma<3, 0>), cudaFuncAttributeMaxDynamicSharedMemorySize, GEMM_SMEM);
    cudaFuncSetAttribute(attn_mma, cudaFuncAttributeMaxDynamicSharedMemorySize, ATT_SMEM);

    // prep: Wqkv transpose + LN1 + zero LN counters
    prep_k<<<7168, 256>>>(Wq, Wk, Wv, x, ln1g, ln1b, pWqkv, pXn);
    // QKV projection (1-pass) -> head-major fp16 q(scaled)/k/v
    gemm_mma<3, 0><<<dim3(QKV_N / 128, TOKENS / 128), 256, GEMM_SMEM>>>(
        pXn, pWqkv, D_MODEL, QKV_N, nullptr, nullptr, nullptr, nullptr,
        pQ, pK, pV, nullptr, nullptr, nullptr);
    // flash attention + absorbed Wo/W1/W2 transposes in tail blocks
    attn_mma<<<dim3(SEQ / 128, BH + 18), 256, ATT_SMEM>>>(
        pQ, pK, pV, pAt, Wo, W1, W2, pWo, pW1, pW2);
    // O projection + bias + residual + FUSED LN2 (last-block per M-tile)
    gemm_mma<1, 1><<<dim3(D_MODEL / 128, TOKENS / 128), 256, GEMM_SMEM>>>(
        pAt, pWo, D_MODEL, D_MODEL, pHid, nullptr, bo, x,
        nullptr, nullptr, nullptr, ln2g, ln2b, pHn);
    // FF1 (1-pass) + bias + GELU
    gemm_mma<2, 0><<<dim3(D_FF / 128, TOKENS / 128), 256, GEMM_SMEM>>>(
        pHn, pW1, D_MODEL, D_FF, nullptr, pFf, b1, nullptr,
        nullptr, nullptr, nullptr, nullptr, nullptr, nullptr);
    // FF2 (1-pass) + bias + residual -> out
    gemm_mma<1, 0><<<dim3(D_MODEL / 128, TOKENS / 128), 256, GEMM_SMEM>>>(
        pFf, pW2, D_FF, D_MODEL, out, nullptr, b2, pHid,
        nullptr, nullptr, nullptr, nullptr, nullptr, nullptr);
}

// round 16
// speedup vs baseline: 1.0477x; 1.0477x over previous
#include <cuda_runtime.h>
#include <cuda_fp16.h>
#include <math.h>
#include <stdint.h>

#define D_MODEL 1024
#define N_HEADS 16
#define D_HEAD 64
#define D_FF 4096
#define SEQ 2048
#define BATCH 2
#define TOKENS (BATCH * SEQ)
#define QKV_N (3 * D_MODEL)
#define BH (BATCH * N_HEADS)

typedef __half hf;

// ---------------- scratch ----------------
__device__ hf g_WqkvT[QKV_N * D_MODEL];
__device__ hf g_WoT[D_MODEL * D_MODEL];
__device__ hf g_W1T[D_FF * D_MODEL];
__device__ hf g_W2T[D_MODEL * D_FF];
__device__ hf g_xn[TOKENS * D_MODEL];
// head-major QKV: [bh][s][64]
__device__ hf g_q[BH * SEQ * D_HEAD];
__device__ hf g_k[BH * SEQ * D_HEAD];
__device__ hf g_v[BH * SEQ * D_HEAD];
__device__ hf g_at[TOKENS * D_MODEL];
__device__ float g_hidden[TOKENS * D_MODEL];
__device__ hf g_hn[TOKENS * D_MODEL];
__device__ hf g_ff[(size_t)TOKENS * D_FF];

__device__ __forceinline__ uint32_t smem_to_u32(const void* p) {
    uint32_t a;
    asm("{ .reg .u64 t; cvta.to.shared.u64 t, %1; cvt.u32.u64 %0, t; }"
        : "=r"(a) : "l"(p));
    return a;
}
__device__ __forceinline__ void cp_async16(uint32_t smem, const void* gmem) {
    asm volatile("cp.async.cg.shared.global [%0], [%1], 16;" :: "r"(smem), "l"(gmem));
}
__device__ __forceinline__ void cp_commit() { asm volatile("cp.async.commit_group;"); }
template <int N>
__device__ __forceinline__ void cp_wait() { asm volatile("cp.async.wait_group %0;" :: "n"(N)); }

__device__ __forceinline__ void ldm_x4(uint32_t& r0, uint32_t& r1, uint32_t& r2, uint32_t& r3,
                                       uint32_t addr) {
    asm volatile("ldmatrix.sync.aligned.m8n8.x4.shared.b16 {%0,%1,%2,%3}, [%4];"
                 : "=r"(r0), "=r"(r1), "=r"(r2), "=r"(r3) : "r"(addr));
}
__device__ __forceinline__ void ldm_x4_t(uint32_t& r0, uint32_t& r1, uint32_t& r2, uint32_t& r3,
                                         uint32_t addr) {
    asm volatile("ldmatrix.sync.aligned.m8n8.x4.trans.shared.b16 {%0,%1,%2,%3}, [%4];"
                 : "=r"(r0), "=r"(r1), "=r"(r2), "=r"(r3) : "r"(addr));
}
__device__ __forceinline__ void mma_f16(float& c0, float& c1, float& c2, float& c3,
                                        uint32_t a0, uint32_t a1, uint32_t a2, uint32_t a3,
                                        uint32_t b0, uint32_t b1) {
    asm volatile(
        "mma.sync.aligned.m16n8k16.row.col.f32.f16.f16.f32 "
        "{%0,%1,%2,%3}, {%4,%5,%6,%7}, {%8,%9}, {%0,%1,%2,%3};"
        : "+f"(c0), "+f"(c1), "+f"(c2), "+f"(c3)
        : "r"(a0), "r"(a1), "r"(a2), "r"(a3), "r"(b0), "r"(b1));
}

__device__ __forceinline__ float gelu_exact(float v) {
    return 0.5f * v * (1.0f + erff(v * 0.70710678118654752440f));
}

// ---- packed f32x2 helpers (sm_100+ base PTX) ----
__device__ __forceinline__ uint64_t pk2(float a, float b) {
    uint64_t r; asm("mov.b64 %0, {%1, %2};" : "=l"(r) : "f"(a), "f"(b)); return r;
}
__device__ __forceinline__ void upk2(uint64_t v, float& a, float& b) {
    asm("mov.b64 {%0, %1}, %2;" : "=f"(a), "=f"(b) : "l"(v));
}
__device__ __forceinline__ uint64_t add2_(uint64_t a, uint64_t b) {
    uint64_t r; asm("add.rn.f32x2 %0, %1, %2;" : "=l"(r) : "l"(a), "l"(b)); return r;
}
__device__ __forceinline__ uint64_t fma2_(uint64_t a, uint64_t b, uint64_t c) {
    uint64_t r; asm("fma.rn.f32x2 %0, %1, %2, %3;" : "=l"(r) : "l"(a), "l"(b), "l"(c)); return r;
}
// exp2 of two values at once, pure FMA/ALU pipes (no MUFU). inputs expected <= 0.
__device__ __forceinline__ void exp2_pair(float& x0, float& x1) {
    float t0 = fmaxf(x0, -126.0f), t1 = fmaxf(x1, -126.0f);
    uint64_t t = pk2(t0, t1);
    uint64_t fn = add2_(t, pk2(12582912.0f, 12582912.0f));
    float fn0, fn1; upk2(fn, fn0, fn1);
    int n0 = __float_as_int(fn0) - 0x4B400000;
    int n1 = __float_as_int(fn1) - 0x4B400000;
    uint64_t fm = add2_(fn, pk2(-12582912.0f, -12582912.0f));
    uint64_t f = fma2_(fm, pk2(-1.0f, -1.0f), t);  // f = t - (fn - magic)
    uint64_t p = pk2(0.0013333558f, 0.0013333558f);
    p = fma2_(p, f, pk2(0.0096181291f, 0.0096181291f));
    p = fma2_(p, f, pk2(0.0555041087f, 0.0555041087f));
    p = fma2_(p, f, pk2(0.2402265070f, 0.2402265070f));
    p = fma2_(p, f, pk2(0.6931471806f, 0.6931471806f));
    p = fma2_(p, f, pk2(1.0f, 1.0f));
    float p0, p1; upk2(p, p0, p1);
    x0 = __int_as_float(__float_as_int(p0) + (n0 << 23));
    x1 = __int_as_float(__float_as_int(p1) + (n1 << 23));
}

__device__ __forceinline__ uint32_t pack_h(hf a, hf b) {
    __half2 p = __halves2half2(a, b);
    return *(uint32_t*)&p;
}
__device__ __forceinline__ uint32_t pack_hf(float a, float b) {
    return pack_h(__float2half_rn(a), __float2half_rn(b));
}

#define QSCALE 0.18033688011f  // 0.125 * log2(e)

// ---------------- prep: Wqkv transpose + LN1 only (rest hidden in attention) ---------
// blocks [0,3072)    : Wqkv transpose (32x32 tiles)
// blocks [3072,7168) : LN1 rows
__global__ __launch_bounds__(256) void prep_k(
    const float* __restrict__ Wq, const float* __restrict__ Wk, const float* __restrict__ Wv,
    const float* __restrict__ x, const float* __restrict__ g, const float* __restrict__ b,
    hf* __restrict__ dQkv, hf* __restrict__ oXn) {
    __shared__ float t[32][33];
    __shared__ float red[2][8];
    const int bid = blockIdx.x;
    const int tid = threadIdx.x;

    if (bid < 3072) {
        int kt = bid & 31, nt = bid >> 5;
        int k0 = kt * 32, n0 = nt * 32;
        int w = n0 >> 10, h = (n0 >> 6) & 15;
        const float* W = (w == 0) ? Wq : (w == 1) ? Wk : Wv;
        const float* src = W + (size_t)h * D_MODEL * D_HEAD;
        int srcCol = n0 & 63;
        const int tx = tid & 31, ty = tid >> 5;
#pragma unroll
        for (int i = 0; i < 4; i++)
            t[ty + i * 8][tx] = src[(size_t)(k0 + ty + i * 8) * 64 + srcCol + tx];
        __syncthreads();
#pragma unroll
        for (int i = 0; i < 4; i++) {
            size_t o = (size_t)(n0 + ty + i * 8) * D_MODEL + k0 + tx;
            dQkv[o] = __float2half_rn(t[tx][ty + i * 8]);
        }
    } else {
        int row = bid - 3072;
        const float4* xr = (const float4*)(x + (size_t)row * D_MODEL);
        float4 v = xr[tid];
        float s = v.x + v.y + v.z + v.w;
        float ss = v.x * v.x + v.y * v.y + v.z * v.z + v.w * v.w;
#pragma unroll
        for (int of = 16; of > 0; of >>= 1) {
            s += __shfl_xor_sync(0xffffffffu, s, of);
            ss += __shfl_xor_sync(0xffffffffu, ss, of);
        }
        int w = tid >> 5, l = tid & 31;
        if (l == 0) { red[0][w] = s; red[1][w] = ss; }
        __syncthreads();
        if (tid < 32) {
            s = (l < 8) ? red[0][l] : 0.f;
            ss = (l < 8) ? red[1][l] : 0.f;
#pragma unroll
            for (int of = 4; of > 0; of >>= 1) {
                s += __shfl_xor_sync(0xffffffffu, s, of);
                ss += __shfl_xor_sync(0xffffffffu, ss, of);
            }
            if (l == 0) { red[0][0] = s; red[1][0] = ss; }
        }
        __syncthreads();
        float mu = red[0][0] * (1.0f / D_MODEL);
        float var = red[1][0] * (1.0f / D_MODEL) - mu * mu;
        float r = rsqrtf(var + 1e-5f);
        float4 gv = ((const float4*)g)[tid];
        float4 bv = ((const float4*)b)[tid];
        float o0 = (v.x - mu) * r * gv.x + bv.x;
        float o1 = (v.y - mu) * r * gv.y + bv.y;
        float o2 = (v.z - mu) * r * gv.z + bv.z;
        float o3 = (v.w - mu) * r * gv.w + bv.w;
        size_t base = (size_t)row * D_MODEL + tid * 4;
        *(uint32_t*)(oXn + base) = pack_hf(o0, o1);
        *(uint32_t*)(oXn + base + 2) = pack_hf(o2, o3);
    }
}

// ---------------- standalone LayerNorm (LN2) -> fp16 ----------------
__global__ __launch_bounds__(256) void layernorm_k(const float* __restrict__ x,
                                                   const float* __restrict__ g,
                                                   const float* __restrict__ b,
                                                   hf* __restrict__ o) {
    __shared__ float red[2][8];
    int row = blockIdx.x;
    int tid = threadIdx.x;
    const float4* xr = (const float4*)(x + (size_t)row * D_MODEL);
    float4 v = xr[tid];
    float s = v.x + v.y + v.z + v.w;
    float ss = v.x * v.x + v.y * v.y + v.z * v.z + v.w * v.w;
#pragma unroll
    for (int of = 16; of > 0; of >>= 1) {
        s += __shfl_xor_sync(0xffffffffu, s, of);
        ss += __shfl_xor_sync(0xffffffffu, ss, of);
    }
    int w = tid >> 5, l = tid & 31;
    if (l == 0) { red[0][w] = s; red[1][w] = ss; }
    __syncthreads();
    if (tid < 32) {
        s = (l < 8) ? red[0][l] : 0.f;
        ss = (l < 8) ? red[1][l] : 0.f;
#pragma unroll
        for (int of = 4; of > 0; of >>= 1) {
            s += __shfl_xor_sync(0xffffffffu, s, of);
            ss += __shfl_xor_sync(0xffffffffu, ss, of);
        }
        if (l == 0) { red[0][0] = s; red[1][0] = ss; }
    }
    __syncthreads();
    float mu = red[0][0] * (1.0f / D_MODEL);
    float var = red[1][0] * (1.0f / D_MODEL) - mu * mu;
    float r = rsqrtf(var + 1e-5f);
    float4 gv = ((const float4*)g)[tid];
    float4 bv = ((const float4*)b)[tid];
    float o0 = (v.x - mu) * r * gv.x + bv.x;
    float o1 = (v.y - mu) * r * gv.y + bv.y;
    float o2 = (v.z - mu) * r * gv.z + bv.z;
    float o3 = (v.w - mu) * r * gv.w + bv.w;
    size_t base = (size_t)row * D_MODEL + tid * 4;
    *(uint32_t*)(o + base) = pack_hf(o0, o1);
    *(uint32_t*)(o + base + 2) = pack_hf(o2, o3);
}

// ---------------- fp16 HMMA GEMM, 1 pass, 128x128x32 tiles ----------------
// EPI: 1 bias+residual fp32 C; 2 bias+GELU fp16; 3 QKV head-major (Q scaled)
#define GSTAGES 3
#define STAGE_BYTES 16384

template <int EPI>
__global__ __launch_bounds__(256, 2) void gemm_mma(
    const hf* __restrict__ A, const hf* __restrict__ B,
    int K, int N,
    float* __restrict__ C, hf* __restrict__ Ch,
    const float* __restrict__ bias, const float* __restrict__ res,
    hf* __restrict__ Qd, hf* __restrict__ Kd, hf* __restrict__ Vd) {
    extern __shared__ char smem[];
    const uint32_t sb = smem_to_u32(smem);
    const int tid = threadIdx.x;
    const int lane = tid & 31;
    const int warp = tid >> 5;
    const int warpM = warp & 3, warpN = warp >> 2;
    const int bn = blockIdx.x * 128, bm = blockIdx.y * 128;

    const size_t rstrideB = (size_t)K * 2;
    const char* gA = (const char*)A + (size_t)bm * K * 2;
    const char* gB = (const char*)B + (size_t)bn * K * 2;

    const int NK = K >> 5;

    auto issue_chunk = [&](int c) {
        const uint32_t stg = sb + (uint32_t)(c % GSTAGES) * STAGE_BYTES;
        const size_t goff = (size_t)c * 64;
#pragma unroll
        for (int j = 0; j < 4; j++) {
            int id = tid + j * 256;
            int arr = id >> 9;
            int row = (id >> 2) & 127;
            int seg = id & 3;
            const char* src = (arr ? gB : gA) + goff + (size_t)row * rstrideB + seg * 16;
            uint32_t dst = stg + (uint32_t)arr * 8192 + (uint32_t)row * 64 +
                           ((uint32_t)(seg ^ ((row >> 1) & 3)) << 4);
            cp_async16(dst, src);
        }
    };

    const int aRow = warpM * 32 + (lane & 15);
    const int aKh = lane >> 4;
    const uint32_t aSw = (aRow >> 1) & 3;
    const uint32_t aRowB = (uint32_t)aRow * 64;
    const int bRowBase = warpN * 64 + (lane & 15);
    const int bKh = lane >> 4;
    const uint32_t bSw = (bRowBase >> 1) & 3;
    const uint32_t bRowB = (uint32_t)bRowBase * 64;

    float acc[2][8][4];
#pragma unroll
    for (int i = 0; i < 2; i++)
#pragma unroll
        for (int j = 0; j < 8; j++)
#pragma unroll
            for (int q = 0; q < 4; q++) acc[i][j][q] = 0.f;

#pragma unroll
    for (int s = 0; s < GSTAGES - 1; s++) { issue_chunk(s); cp_commit(); }

    for (int c = 0; c < NK; c++) {
        cp_wait<GSTAGES - 2>();
        __syncthreads();
        const uint32_t stg = sb + (uint32_t)(c % GSTAGES) * STAGE_BYTES;
#pragma unroll
        for (int k16 = 0; k16 < 2; k16++) {
            const uint32_t aSeg = ((uint32_t)(k16 * 2 + aKh) ^ aSw) << 4;
            const uint32_t bSeg = ((uint32_t)(k16 * 2 + bKh) ^ bSw) << 4;
            uint32_t ah[2][4], bh[4][4];
#pragma unroll
            for (int i = 0; i < 2; i++)
                ldm_x4(ah[i][0], ah[i][1], ah[i][2], ah[i][3],
                       stg + aRowB + (uint32_t)i * 16 * 64 + aSeg);
#pragma unroll
            for (int t = 0; t < 4; t++)
                ldm_x4(bh[t][0], bh[t][1], bh[t][2], bh[t][3],
                       stg + 8192 + bRowB + (uint32_t)t * 16 * 64 + bSeg);
#pragma unroll
            for (int i = 0; i < 2; i++)
#pragma unroll
                for (int t = 0; t < 4; t++) {
                    float* c0 = acc[i][2 * t];
                    float* c1 = acc[i][2 * t + 1];
                    mma_f16(c0[0], c0[1], c0[2], c0[3],
                            ah[i][0], ah[i][1], ah[i][2], ah[i][3], bh[t][0], bh[t][2]);
                    mma_f16(c1[0], c1[1], c1[2], c1[3],
                            ah[i][0], ah[i][1], ah[i][2], ah[i][3], bh[t][1], bh[t][3]);
                }
        }
        __syncthreads();
        if (c + GSTAGES - 1 < NK) issue_chunk(c + GSTAGES - 1);
        cp_commit();
    }

    const int gRow = lane >> 2;
    const int gCol = (lane & 3) * 2;
#pragma unroll
    for (int i = 0; i < 2; i++) {
#pragma unroll
        for (int j = 0; j < 8; j++) {
            int row = bm + warpM * 32 + i * 16 + gRow;
            int col = bn + warpN * 64 + j * 8 + gCol;
#pragma unroll
            for (int half = 0; half < 2; half++) {
                int r = row + half * 8;
                float v0 = acc[i][j][half * 2 + 0];
                float v1 = acc[i][j][half * 2 + 1];
                if (EPI == 1 || EPI == 2) {
                    float2 bb = *(const float2*)(bias + col);
                    v0 += bb.x; v1 += bb.y;
                }
                if (EPI == 1) {
                    float2 rv = *(const float2*)(res + (size_t)r * N + col);
                    v0 += rv.x; v1 += rv.y;
                    *(float2*)(C + (size_t)r * N + col) = make_float2(v0, v1);
                } else if (EPI == 2) {
                    v0 = gelu_exact(v0); v1 = gelu_exact(v1);
                    *(uint32_t*)(Ch + (size_t)r * N + col) = pack_hf(v0, v1);
                } else if (EPI == 3) {
                    int which = col >> 10;
                    int h = (col >> 6) & 15;
                    int e = col & 63;
                    int bb = r >> 11, s = r & 2047;
                    size_t o = (((size_t)(bb * 16 + h)) * SEQ + s) * D_HEAD + e;
                    if (which == 0) { v0 *= QSCALE; v1 *= QSCALE; }
                    hf* dst = (which == 0) ? Qd : (which == 1) ? Kd : Vd;
                    *(uint32_t*)(dst + o) = pack_hf(v0, v1);
                }
            }
        }
    }
}

// ---------------- fp16 HMMA flash attention + absorbed weight transposes ------------
// grid (16, 32 + 18): by<32 = attention; by>=32 = Wo/W1/W2 transpose tiles (filling
// the attention tail wave; outputs needed only by later GEMMs).
// smem: Q 0 (16KB); stage s at 16384 + s*16384: K 0, V 8192
#define ATT_SMEM (16384 + 2 * 16384)
#define TRB 288  // transpose blocks = 16 * 18

__global__ __launch_bounds__(256, 2) void attn_mma(
    const hf* __restrict__ q_g, const hf* __restrict__ k_g, const hf* __restrict__ v_g,
    hf* __restrict__ oh,
    const float* __restrict__ Wo, const float* __restrict__ W1, const float* __restrict__ W2,
    hf* __restrict__ dWo, hf* __restrict__ dW1, hf* __restrict__ dW2) {
    extern __shared__ char smem[];
    const int tid = threadIdx.x;

    if (blockIdx.y >= BH) {
        // ---- transpose path: 9216 32x32 tiles over 288 blocks, 32 tiles each ----
        float (*t)[33] = (float(*)[33])smem;
        const int tb = (blockIdx.y - BH) * 16 + blockIdx.x;
        const int tx = tid & 31, ty = tid >> 5;
#pragma unroll 1
        for (int it = 0; it < 32; it++) {
            int tile = tb + it * TRB;  // 0..9215
            const float* src;
            hf* dst;
            int k0, n0, srcStride, Kd;
            if (tile < 1024) {
                k0 = (tile & 31) * 32; n0 = (tile >> 5) * 32;
                src = Wo; srcStride = D_MODEL; dst = dWo; Kd = D_MODEL;
            } else if (tile < 5120) {
                int tt = tile - 1024;
                k0 = (tt & 31) * 32; n0 = (tt >> 5) * 32;
                src = W1; srcStride = D_FF; dst = dW1; Kd = D_MODEL;
            } else {
                int tt = tile - 5120;
                k0 = (tt & 127) * 32; n0 = (tt >> 7) * 32;
                src = W2; srcStride = D_MODEL; dst = dW2; Kd = D_FF;
            }
#pragma unroll
            for (int i = 0; i < 4; i++)
                t[ty + i * 8][tx] = src[(size_t)(k0 + ty + i * 8) * srcStride + n0 + tx];
            __syncthreads();
#pragma unroll
            for (int i = 0; i < 4; i++) {
                size_t o = (size_t)(n0 + ty + i * 8) * Kd + k0 + tx;
                dst[o] = __float2half_rn(t[tx][ty + i * 8]);
            }
            __syncthreads();
        }
        return;
    }

    const uint32_t sb = smem_to_u32(smem);
    const int lane = tid & 31;
    const int warp = tid >> 5;
    const int bh = blockIdx.y;
    const int q0 = blockIdx.x * 128;

    const char* qb = (const char*)(q_g + ((size_t)bh * SEQ + q0) * D_HEAD);
    const char* kb = (const char*)(k_g + (size_t)bh * SEQ * D_HEAD);
    const char* vb = (const char*)(v_g + (size_t)bh * SEQ * D_HEAD);

    {
#pragma unroll
        for (int j = 0; j < 4; j++) {
            int id = tid + j * 256;
            int row = (id >> 3) & 127, seg = id & 7;
            uint32_t dst = sb + (uint32_t)row * 128 + ((uint32_t)(seg ^ (row & 7)) << 4);
            cp_async16(dst, qb + (size_t)row * 128 + seg * 16);
        }
    }
    auto issue_kv = [&](int kt) {
        const uint32_t stg = sb + 16384 + (uint32_t)(kt & 1) * 16384;
        const size_t gof = (size_t)kt * 64 * 128;
#pragma unroll
        for (int j = 0; j < 4; j++) {
            int id = tid + j * 256;
            int arr = id >> 9, row = (id >> 3) & 63, seg = id & 7;
            const char* src = ((arr == 0) ? kb : vb) + gof + (size_t)row * 128 + seg * 16;
            uint32_t dst = stg + (uint32_t)arr * 8192 + (uint32_t)row * 128 +
                           ((uint32_t)(seg ^ (row & 7)) << 4);
            cp_async16(dst, src);
        }
    };

    issue_kv(0);
    cp_commit();
    issue_kv(1);
    cp_commit();

    float accO[8][4];
#pragma unroll
    for (int t = 0; t < 8; t++)
#pragma unroll
        for (int q = 0; q < 4; q++) accO[t][q] = 0.f;
    float m0 = -1e30f, m1 = -1e30f, l0 = 0.f, l1 = 0.f;

    uint32_t qf[4][4];
    const int qRow = warp * 16 + (lane & 15);
    const uint32_t qSw = (uint32_t)(qRow & 7);
    const uint32_t qRowB = (uint32_t)qRow * 128;

    const int NT = SEQ / 64;
    for (int kt = 0; kt < NT; kt++) {
        cp_wait<1>();
        __syncthreads();
        if (kt == 0) {
#pragma unroll
            for (int ks = 0; ks < 4; ks++) {
                uint32_t seg = ((uint32_t)(ks * 2 + (lane >> 4)) ^ qSw) << 4;
                ldm_x4(qf[ks][0], qf[ks][1], qf[ks][2], qf[ks][3], sb + qRowB + seg);
            }
        }
        const uint32_t stg = sb + 16384 + (uint32_t)(kt & 1) * 16384;

        // ---- S = Q K^T (1 pass) ----
        float S[8][4];
#pragma unroll
        for (int t = 0; t < 8; t++)
#pragma unroll
            for (int q = 0; q < 4; q++) S[t][q] = 0.f;

        const int nRow = lane & 15;
        const int kh4 = lane >> 4;
#pragma unroll
        for (int ks = 0; ks < 4; ks++) {
            uint32_t kh[4][4];
#pragma unroll
            for (int g = 0; g < 4; g++) {
                int row = g * 16 + nRow;
                uint32_t seg = ((uint32_t)(ks * 2 + kh4) ^ (uint32_t)(row & 7)) << 4;
                ldm_x4(kh[g][0], kh[g][1], kh[g][2], kh[g][3],
                       stg + (uint32_t)row * 128 + seg);
            }
#pragma unroll
            for (int g = 0; g < 4; g++) {
                float* c0 = S[2 * g];
                float* c1 = S[2 * g + 1];
                mma_f16(c0[0], c0[1], c0[2], c0[3],
                        qf[ks][0], qf[ks][1], qf[ks][2], qf[ks][3], kh[g][0], kh[g][2]);
                mma_f16(c1[0], c1[1], c1[2], c1[3],
                        qf[ks][0], qf[ks][1], qf[ks][2], qf[ks][3], kh[g][1], kh[g][3]);
            }
        }

        // ---- online softmax (f32x2 packed exp2, base-2 domain) ----
        float mx0 = S[0][0], mx1 = S[0][2];
#pragma unroll
        for (int t = 0; t < 8; t++) {
            mx0 = fmaxf(mx0, fmaxf(S[t][0], S[t][1]));
            mx1 = fmaxf(mx1, fmaxf(S[t][2], S[t][3]));
        }
        mx0 = fmaxf(mx0, __shfl_xor_sync(0xffffffffu, mx0, 1));
        mx0 = fmaxf(mx0, __shfl_xor_sync(0xffffffffu, mx0, 2));
        mx1 = fmaxf(mx1, __shfl_xor_sync(0xffffffffu, mx1, 1));
        mx1 = fmaxf(mx1, __shfl_xor_sync(0xffffffffu, mx1, 2));
        float mn0 = fmaxf(m0, mx0), mn1 = fmaxf(m1, mx1);
        float cr0 = m0 - mn0, cr1 = m1 - mn1;
        exp2_pair(cr0, cr1);
        m0 = mn0; m1 = mn1;
        float sum0 = 0.f, sum1 = 0.f;
#pragma unroll
        for (int t = 0; t < 8; t++) {
            float a0 = S[t][0] - mn0, a1 = S[t][1] - mn0;
            float b0 = S[t][2] - mn1, b1 = S[t][3] - mn1;
            exp2_pair(a0, a1);
            exp2_pair(b0, b1);
            S[t][0] = a0; S[t][1] = a1; S[t][2] = b0; S[t][3] = b1;
            sum0 += a0 + a1;
            sum1 += b0 + b1;
        }
        sum0 += __shfl_xor_sync(0xffffffffu, sum0, 1);
        sum0 += __shfl_xor_sync(0xffffffffu, sum0, 2);
        sum1 += __shfl_xor_sync(0xffffffffu, sum1, 1);
        sum1 += __shfl_xor_sync(0xffffffffu, sum1, 2);
        l0 = l0 * cr0 + sum0;
        l1 = l1 * cr1 + sum1;
#pragma unroll
        for (int t = 0; t < 8; t++) {
            accO[t][0] *= cr0; accO[t][1] *= cr0;
            accO[t][2] *= cr1; accO[t][3] *= cr1;
        }

        // ---- O += P V (1 pass) ----
        const int vRow16 = lane & 15;
        const int vEh = lane >> 4;
#pragma unroll
        for (int ks = 0; ks < 4; ks++) {
            uint32_t pa[4];
            pa[0] = pack_hf(S[2 * ks][0], S[2 * ks][1]);
            pa[1] = pack_hf(S[2 * ks][2], S[2 * ks][3]);
            pa[2] = pack_hf(S[2 * ks + 1][0], S[2 * ks + 1][1]);
            pa[3] = pack_hf(S[2 * ks + 1][2], S[2 * ks + 1][3]);

            uint32_t vh[4][4];
#pragma unroll
            for (int g = 0; g < 4; g++) {
                int row = ks * 16 + vRow16;
                uint32_t seg = ((uint32_t)(g * 2 + vEh) ^ (uint32_t)(row & 7)) << 4;
                ldm_x4_t(vh[g][0], vh[g][1], vh[g][2], vh[g][3],
                         stg + 8192 + (uint32_t)row * 128 + seg);
            }
#pragma unroll
            for (int g = 0; g < 4; g++) {
                float* c0 = accO[2 * g];
                float* c1 = accO[2 * g + 1];
                mma_f16(c0[0], c0[1], c0[2], c0[3],
                        pa[0], pa[1], pa[2], pa[3], vh[g][0], vh[g][1]);
                mma_f16(c1[0], c1[1], c1[2], c1[3],
                        pa[0], pa[1], pa[2], pa[3], vh[g][2], vh[g][3]);
            }
        }
        __syncthreads();
        if (kt + 2 < NT) issue_kv(kt + 2);
        cp_commit();
    }

    // ---- epilogue ----
    float inv0 = 1.0f / l0, inv1 = 1.0f / l1;
    const int b = bh >> 4, h = bh & 15;
    const int r1 = q0 + warp * 16 + (lane >> 2);
    const int r2 = r1 + 8;
    size_t t1 = ((size_t)(b * SEQ) + r1) * D_MODEL + h * D_HEAD;
    size_t t2 = ((size_t)(b * SEQ) + r2) * D_MODEL + h * D_HEAD;
#pragma unroll
    for (int t = 0; t < 8; t++) {
        int e = t * 8 + (lane & 3) * 2;
        *(uint32_t*)(oh + t1 + e) = pack_hf(accO[t][0] * inv0, accO[t][1] * inv0);
        *(uint32_t*)(oh + t2 + e) = pack_hf(accO[t][2] * inv1, accO[t][3] * inv1);
    }
}

// ---------------- launch ----------------
extern "C" void kernel_launch(void* const* d_in, const int* in_sizes, int n_in,
                              void* d_out, int out_size) {
    const float* x    = (const float*)d_in[0];
    const float* Wq   = (const float*)d_in[1];
    const float* Wk   = (const float*)d_in[2];
    const float* Wv   = (const float*)d_in[3];
    const float* Wo   = (const float*)d_in[4];
    const float* bo   = (const float*)d_in[5];
    const float* ln1g = (const float*)d_in[6];
    const float* ln1b = (const float*)d_in[7];
    const float* ln2g = (const float*)d_in[8];
    const float* ln2b = (const float*)d_in[9];
    const float* W1   = (const float*)d_in[10];
    const float* b1   = (const float*)d_in[11];
    const float* W2   = (const float*)d_in[12];
    const float* b2   = (const float*)d_in[13];
    float* out = (float*)d_out;

    hf *pWqkv, *pWo, *pW1, *pW2, *pXn, *pAt, *pHn, *pFf, *pQ, *pK, *pV;
    float* pHid;
    cudaGetSymbolAddress((void**)&pWqkv, g_WqkvT);
    cudaGetSymbolAddress((void**)&pWo, g_WoT);
    cudaGetSymbolAddress((void**)&pW1, g_W1T);
    cudaGetSymbolAddress((void**)&pW2, g_W2T);
    cudaGetSymbolAddress((void**)&pXn, g_xn);
    cudaGetSymbolAddress((void**)&pAt, g_at);
    cudaGetSymbolAddress((void**)&pHn, g_hn);
    cudaGetSymbolAddress((void**)&pFf, g_ff);
    cudaGetSymbolAddress((void**)&pQ, g_q);
    cudaGetSymbolAddress((void**)&pK, g_k);
    cudaGetSymbolAddress((void**)&pV, g_v);
    cudaGetSymbolAddress((void**)&pHid, g_hidden);

    const int GEMM_SMEM = GSTAGES * STAGE_BYTES;  // 49152
    cudaFuncSetAttribute(gemm_mma<1>, cudaFuncAttributeMaxDynamicSharedMemorySize, GEMM_SMEM);
    cudaFuncSetAttribute(gemm_mma<2>, cudaFuncAttributeMaxDynamicSharedMemorySize, GEMM_SMEM);
    cudaFuncSetAttribute(gemm_mma<3>, cudaFuncAttributeMaxDynamicSharedMemorySize, GEMM_SMEM);
    cudaFuncSetAttribute(attn_mma, cudaFuncAttributeMaxDynamicSharedMemorySize, ATT_SMEM);

    // prep: Wqkv transpose + LN1 only
    prep_k<<<7168, 256>>>(Wq, Wk, Wv, x, ln1g, ln1b, pWqkv, pXn);
    // QKV projection (1-pass) -> head-major fp16 q(scaled)/k/v
    gemm_mma<3><<<dim3(QKV_N / 128, TOKENS / 128), 256, GEMM_SMEM>>>(
        pXn, pWqkv, D_MODEL, QKV_N, nullptr, nullptr, nullptr, nullptr, pQ, pK, pV);
    // flash attention + absorbed Wo/W1/W2 transposes in tail blocks
    attn_mma<<<dim3(SEQ / 128, BH + 18), 256, ATT_SMEM>>>(
        pQ, pK, pV, pAt, Wo, W1, W2, pWo, pW1, pW2);
    // O projection (unsplit) + bias + residual
    gemm_mma<1><<<dim3(D_MODEL / 128, TOKENS / 128), 256, GEMM_SMEM>>>(
        pAt, pWo, D_MODEL, D_MODEL, pHid, nullptr, bo, x, nullptr, nullptr, nullptr);
    layernorm_k<<<TOKENS, 256>>>(pHid, ln2g, ln2b, pHn);
    // FF1 (1-pass) + bias + GELU
    gemm_mma<2><<<dim3(D_FF / 128, TOKENS / 128), 256, GEMM_SMEM>>>(
        pHn, pW1, D_MODEL, D_FF, nullptr, pFf, b1, nullptr, nullptr, nullptr, nullptr);
    // FF2 (1-pass) + bias + residual -> out
    gemm_mma<1><<<dim3(D_MODEL / 128, TOKENS / 128), 256, GEMM_SMEM>>>(
        pFf, pW2, D_FF, D_MODEL, out, nullptr, b2, pHid, nullptr, nullptr, nullptr);
}

// round 17
// speedup vs baseline: 1.0686x; 1.0199x over previous
#include <cuda_runtime.h>
#include <cuda_fp16.h>
#include <math.h>
#include <stdint.h>

#define D_MODEL 1024
#define N_HEADS 16
#define D_HEAD 64
#define D_FF 4096
#define SEQ 2048
#define BATCH 2
#define TOKENS (BATCH * SEQ)
#define QKV_N (3 * D_MODEL)
#define BH (BATCH * N_HEADS)

typedef __half hf;

// ---------------- scratch ----------------
__device__ hf g_WqkvT[QKV_N * D_MODEL];
__device__ hf g_WoT[D_MODEL * D_MODEL];
__device__ hf g_W1T[D_FF * D_MODEL];
__device__ hf g_W2T[D_MODEL * D_FF];
__device__ hf g_xn[TOKENS * D_MODEL];
// head-major QKV: [bh][s][64]
__device__ hf g_q[BH * SEQ * D_HEAD];
__device__ hf g_k[BH * SEQ * D_HEAD];
__device__ hf g_v[BH * SEQ * D_HEAD];
__device__ hf g_at[TOKENS * D_MODEL];
__device__ float g_hidden[TOKENS * D_MODEL];
__device__ hf g_hn[TOKENS * D_MODEL];
__device__ hf g_ff[(size_t)TOKENS * D_FF];

__device__ __forceinline__ uint32_t smem_to_u32(const void* p) {
    uint32_t a;
    asm("{ .reg .u64 t; cvta.to.shared.u64 t, %1; cvt.u32.u64 %0, t; }"
        : "=r"(a) : "l"(p));
    return a;
}
__device__ __forceinline__ void cp_async16(uint32_t smem, const void* gmem) {
    asm volatile("cp.async.cg.shared.global [%0], [%1], 16;" :: "r"(smem), "l"(gmem));
}
__device__ __forceinline__ void cp_commit() { asm volatile("cp.async.commit_group;"); }
template <int N>
__device__ __forceinline__ void cp_wait() { asm volatile("cp.async.wait_group %0;" :: "n"(N)); }

__device__ __forceinline__ void ldm_x4(uint32_t& r0, uint32_t& r1, uint32_t& r2, uint32_t& r3,
                                       uint32_t addr) {
    asm volatile("ldmatrix.sync.aligned.m8n8.x4.shared.b16 {%0,%1,%2,%3}, [%4];"
                 : "=r"(r0), "=r"(r1), "=r"(r2), "=r"(r3) : "r"(addr));
}
__device__ __forceinline__ void ldm_x4_t(uint32_t& r0, uint32_t& r1, uint32_t& r2, uint32_t& r3,
                                         uint32_t addr) {
    asm volatile("ldmatrix.sync.aligned.m8n8.x4.trans.shared.b16 {%0,%1,%2,%3}, [%4];"
                 : "=r"(r0), "=r"(r1), "=r"(r2), "=r"(r3) : "r"(addr));
}
__device__ __forceinline__ void mma_f16(float& c0, float& c1, float& c2, float& c3,
                                        uint32_t a0, uint32_t a1, uint32_t a2, uint32_t a3,
                                        uint32_t b0, uint32_t b1) {
    asm volatile(
        "mma.sync.aligned.m16n8k16.row.col.f32.f16.f16.f32 "
        "{%0,%1,%2,%3}, {%4,%5,%6,%7}, {%8,%9}, {%0,%1,%2,%3};"
        : "+f"(c0), "+f"(c1), "+f"(c2), "+f"(c3)
        : "r"(a0), "r"(a1), "r"(a2), "r"(a3), "r"(b0), "r"(b1));
}

__device__ __forceinline__ float gelu_exact(float v) {
    return 0.5f * v * (1.0f + erff(v * 0.70710678118654752440f));
}

// ---- packed f32x2 helpers (sm_100+ base PTX) ----
__device__ __forceinline__ uint64_t pk2(float a, float b) {
    uint64_t r; asm("mov.b64 %0, {%1, %2};" : "=l"(r) : "f"(a), "f"(b)); return r;
}
__device__ __forceinline__ void upk2(uint64_t v, float& a, float& b) {
    asm("mov.b64 {%0, %1}, %2;" : "=f"(a), "=f"(b) : "l"(v));
}
__device__ __forceinline__ uint64_t add2_(uint64_t a, uint64_t b) {
    uint64_t r; asm("add.rn.f32x2 %0, %1, %2;" : "=l"(r) : "l"(a), "l"(b)); return r;
}
__device__ __forceinline__ uint64_t fma2_(uint64_t a, uint64_t b, uint64_t c) {
    uint64_t r; asm("fma.rn.f32x2 %0, %1, %2, %3;" : "=l"(r) : "l"(a), "l"(b), "l"(c)); return r;
}
// exp2 of two values at once, pure FMA/ALU pipes (no MUFU). inputs expected <= 0.
__device__ __forceinline__ void exp2_pair(float& x0, float& x1) {
    float t0 = fmaxf(x0, -126.0f), t1 = fmaxf(x1, -126.0f);
    uint64_t t = pk2(t0, t1);
    uint64_t fn = add2_(t, pk2(12582912.0f, 12582912.0f));
    float fn0, fn1; upk2(fn, fn0, fn1);
    int n0 = __float_as_int(fn0) - 0x4B400000;
    int n1 = __float_as_int(fn1) - 0x4B400000;
    uint64_t fm = add2_(fn, pk2(-12582912.0f, -12582912.0f));
    uint64_t f = fma2_(fm, pk2(-1.0f, -1.0f), t);  // f = t - (fn - magic)
    uint64_t p = pk2(0.0013333558f, 0.0013333558f);
    p = fma2_(p, f, pk2(0.0096181291f, 0.0096181291f));
    p = fma2_(p, f, pk2(0.0555041087f, 0.0555041087f));
    p = fma2_(p, f, pk2(0.2402265070f, 0.2402265070f));
    p = fma2_(p, f, pk2(0.6931471806f, 0.6931471806f));
    p = fma2_(p, f, pk2(1.0f, 1.0f));
    float p0, p1; upk2(p, p0, p1);
    x0 = __int_as_float(__float_as_int(p0) + (n0 << 23));
    x1 = __int_as_float(__float_as_int(p1) + (n1 << 23));
}

__device__ __forceinline__ uint32_t pack_h(hf a, hf b) {
    __half2 p = __halves2half2(a, b);
    return *(uint32_t*)&p;
}
__device__ __forceinline__ uint32_t pack_hf(float a, float b) {
    return pack_h(__float2half_rn(a), __float2half_rn(b));
}

#define QSCALE 0.18033688011f  // 0.125 * log2(e)

// ---------------- prep: Wqkv transpose + LN1 only (rest hidden in attention) ---------
// blocks [0,3072)    : Wqkv transpose (32x32 tiles)
// blocks [3072,7168) : LN1 rows
__global__ __launch_bounds__(256) void prep_k(
    const float* __restrict__ Wq, const float* __restrict__ Wk, const float* __restrict__ Wv,
    const float* __restrict__ x, const float* __restrict__ g, const float* __restrict__ b,
    hf* __restrict__ dQkv, hf* __restrict__ oXn) {
    __shared__ float t[32][33];
    __shared__ float red[2][8];
    const int bid = blockIdx.x;
    const int tid = threadIdx.x;

    if (bid < 3072) {
        int kt = bid & 31, nt = bid >> 5;
        int k0 = kt * 32, n0 = nt * 32;
        int w = n0 >> 10, h = (n0 >> 6) & 15;
        const float* W = (w == 0) ? Wq : (w == 1) ? Wk : Wv;
        const float* src = W + (size_t)h * D_MODEL * D_HEAD;
        int srcCol = n0 & 63;
        const int tx = tid & 31, ty = tid >> 5;
#pragma unroll
        for (int i = 0; i < 4; i++)
            t[ty + i * 8][tx] = src[(size_t)(k0 + ty + i * 8) * 64 + srcCol + tx];
        __syncthreads();
#pragma unroll
        for (int i = 0; i < 4; i++) {
            size_t o = (size_t)(n0 + ty + i * 8) * D_MODEL + k0 + tx;
            dQkv[o] = __float2half_rn(t[tx][ty + i * 8]);
        }
    } else {
        int row = bid - 3072;
        const float4* xr = (const float4*)(x + (size_t)row * D_MODEL);
        float4 v = xr[tid];
        float s = v.x + v.y + v.z + v.w;
        float ss = v.x * v.x + v.y * v.y + v.z * v.z + v.w * v.w;
#pragma unroll
        for (int of = 16; of > 0; of >>= 1) {
            s += __shfl_xor_sync(0xffffffffu, s, of);
            ss += __shfl_xor_sync(0xffffffffu, ss, of);
        }
        int w = tid >> 5, l = tid & 31;
        if (l == 0) { red[0][w] = s; red[1][w] = ss; }
        __syncthreads();
        if (tid < 32) {
            s = (l < 8) ? red[0][l] : 0.f;
            ss = (l < 8) ? red[1][l] : 0.f;
#pragma unroll
            for (int of = 4; of > 0; of >>= 1) {
                s += __shfl_xor_sync(0xffffffffu, s, of);
                ss += __shfl_xor_sync(0xffffffffu, ss, of);
            }
            if (l == 0) { red[0][0] = s; red[1][0] = ss; }
        }
        __syncthreads();
        float mu = red[0][0] * (1.0f / D_MODEL);
        float var = red[1][0] * (1.0f / D_MODEL) - mu * mu;
        float r = rsqrtf(var + 1e-5f);
        float4 gv = ((const float4*)g)[tid];
        float4 bv = ((const float4*)b)[tid];
        float o0 = (v.x - mu) * r * gv.x + bv.x;
        float o1 = (v.y - mu) * r * gv.y + bv.y;
        float o2 = (v.z - mu) * r * gv.z + bv.z;
        float o3 = (v.w - mu) * r * gv.w + bv.w;
        size_t base = (size_t)row * D_MODEL + tid * 4;
        *(uint32_t*)(oXn + base) = pack_hf(o0, o1);
        *(uint32_t*)(oXn + base + 2) = pack_hf(o2, o3);
    }
}

// ---------------- standalone LayerNorm (LN2) -> fp16 ----------------
__global__ __launch_bounds__(256) void layernorm_k(const float* __restrict__ x,
                                                   const float* __restrict__ g,
                                                   const float* __restrict__ b,
                                                   hf* __restrict__ o) {
    __shared__ float red[2][8];
    int row = blockIdx.x;
    int tid = threadIdx.x;
    const float4* xr = (const float4*)(x + (size_t)row * D_MODEL);
    float4 v = xr[tid];
    float s = v.x + v.y + v.z + v.w;
    float ss = v.x * v.x + v.y * v.y + v.z * v.z + v.w * v.w;
#pragma unroll
    for (int of = 16; of > 0; of >>= 1) {
        s += __shfl_xor_sync(0xffffffffu, s, of);
        ss += __shfl_xor_sync(0xffffffffu, ss, of);
    }
    int w = tid >> 5, l = tid & 31;
    if (l == 0) { red[0][w] = s; red[1][w] = ss; }
    __syncthreads();
    if (tid < 32) {
        s = (l < 8) ? red[0][l] : 0.f;
        ss = (l < 8) ? red[1][l] : 0.f;
#pragma unroll
        for (int of = 4; of > 0; of >>= 1) {
            s += __shfl_xor_sync(0xffffffffu, s, of);
            ss += __shfl_xor_sync(0xffffffffu, ss, of);
        }
        if (l == 0) { red[0][0] = s; red[1][0] = ss; }
    }
    __syncthreads();
    float mu = red[0][0] * (1.0f / D_MODEL);
    float var = red[1][0] * (1.0f / D_MODEL) - mu * mu;
    float r = rsqrtf(var + 1e-5f);
    float4 gv = ((const float4*)g)[tid];
    float4 bv = ((const float4*)b)[tid];
    float o0 = (v.x - mu) * r * gv.x + bv.x;
    float o1 = (v.y - mu) * r * gv.y + bv.y;
    float o2 = (v.z - mu) * r * gv.z + bv.z;
    float o3 = (v.w - mu) * r * gv.w + bv.w;
    size_t base = (size_t)row * D_MODEL + tid * 4;
    *(uint32_t*)(o + base) = pack_hf(o0, o1);
    *(uint32_t*)(o + base + 2) = pack_hf(o2, o3);
}

// ---------------- fp16 HMMA GEMM, 1 pass, 128x128x64 tiles ----------------
// BK=64: 32KB/stage (A 16KB + B 16KB), 128B rows, seg^(row&7) swizzle (attn-proven).
// EPI: 1 bias+residual fp32 C; 2 bias+GELU fp16; 3 QKV head-major (Q scaled)
#define GSTAGES 3
#define STAGE_BYTES 32768

template <int EPI>
__global__ __launch_bounds__(256, 2) void gemm_mma(
    const hf* __restrict__ A, const hf* __restrict__ B,
    int K, int N,
    float* __restrict__ C, hf* __restrict__ Ch,
    const float* __restrict__ bias, const float* __restrict__ res,
    hf* __restrict__ Qd, hf* __restrict__ Kd, hf* __restrict__ Vd) {
    extern __shared__ char smem[];
    const uint32_t sb = smem_to_u32(smem);
    const int tid = threadIdx.x;
    const int lane = tid & 31;
    const int warp = tid >> 5;
    const int warpM = warp & 3, warpN = warp >> 2;
    const int bn = blockIdx.x * 128, bm = blockIdx.y * 128;

    const size_t rstrideB = (size_t)K * 2;
    const char* gA = (const char*)A + (size_t)bm * K * 2;
    const char* gB = (const char*)B + (size_t)bn * K * 2;

    const int NK = K >> 6;  // chunks of 64 elems (128 bytes)

    auto issue_chunk = [&](int c) {
        const uint32_t stg = sb + (uint32_t)(c % GSTAGES) * STAGE_BYTES;
        const size_t goff = (size_t)c * 128;
#pragma unroll
        for (int j = 0; j < 8; j++) {
            int id = tid + j * 256;           // 0..2047
            int arr = id >> 10;               // 0=A, 1=B
            int row = (id >> 3) & 127;
            int seg = id & 7;
            const char* src = (arr ? gB : gA) + goff + (size_t)row * rstrideB + seg * 16;
            uint32_t dst = stg + (uint32_t)arr * 16384 + (uint32_t)row * 128 +
                           ((uint32_t)(seg ^ (row & 7)) << 4);
            cp_async16(dst, src);
        }
    };

    const int aRow = warpM * 32 + (lane & 15);
    const int aKh = lane >> 4;
    const int bRowBase = warpN * 64 + (lane & 15);
    const int bKh = lane >> 4;

    float acc[2][8][4];
#pragma unroll
    for (int i = 0; i < 2; i++)
#pragma unroll
        for (int j = 0; j < 8; j++)
#pragma unroll
            for (int q = 0; q < 4; q++) acc[i][j][q] = 0.f;

#pragma unroll
    for (int s = 0; s < GSTAGES - 1; s++) { issue_chunk(s); cp_commit(); }

    for (int c = 0; c < NK; c++) {
        cp_wait<GSTAGES - 2>();
        __syncthreads();
        const uint32_t stg = sb + (uint32_t)(c % GSTAGES) * STAGE_BYTES;
#pragma unroll
        for (int k16 = 0; k16 < 4; k16++) {
            uint32_t ah[2][4], bh[4][4];
#pragma unroll
            for (int i = 0; i < 2; i++) {
                int row = aRow + i * 16;
                uint32_t seg = ((uint32_t)(k16 * 2 + aKh) ^ (uint32_t)(row & 7)) << 4;
                ldm_x4(ah[i][0], ah[i][1], ah[i][2], ah[i][3],
                       stg + (uint32_t)row * 128 + seg);
            }
#pragma unroll
            for (int t = 0; t < 4; t++) {
                int row = bRowBase + t * 16;
                uint32_t seg = ((uint32_t)(k16 * 2 + bKh) ^ (uint32_t)(row & 7)) << 4;
                ldm_x4(bh[t][0], bh[t][1], bh[t][2], bh[t][3],
                       stg + 16384 + (uint32_t)row * 128 + seg);
            }
#pragma unroll
            for (int i = 0; i < 2; i++)
#pragma unroll
                for (int t = 0; t < 4; t++) {
                    float* c0 = acc[i][2 * t];
                    float* c1 = acc[i][2 * t + 1];
                    mma_f16(c0[0], c0[1], c0[2], c0[3],
                            ah[i][0], ah[i][1], ah[i][2], ah[i][3], bh[t][0], bh[t][2]);
                    mma_f16(c1[0], c1[1], c1[2], c1[3],
                            ah[i][0], ah[i][1], ah[i][2], ah[i][3], bh[t][1], bh[t][3]);
                }
        }
        __syncthreads();
        if (c + GSTAGES - 1 < NK) issue_chunk(c + GSTAGES - 1);
        cp_commit();
    }

    const int gRow = lane >> 2;
    const int gCol = (lane & 3) * 2;
#pragma unroll
    for (int i = 0; i < 2; i++) {
#pragma unroll
        for (int j = 0; j < 8; j++) {
            int row = bm + warpM * 32 + i * 16 + gRow;
            int col = bn + warpN * 64 + j * 8 + gCol;
#pragma unroll
            for (int half = 0; half < 2; half++) {
                int r = row + half * 8;
                float v0 = acc[i][j][half * 2 + 0];
                float v1 = acc[i][j][half * 2 + 1];
                if (EPI == 1 || EPI == 2) {
                    float2 bb = *(const float2*)(bias + col);
                    v0 += bb.x; v1 += bb.y;
                }
                if (EPI == 1) {
                    float2 rv = *(const float2*)(res + (size_t)r * N + col);
                    v0 += rv.x; v1 += rv.y;
                    *(float2*)(C + (size_t)r * N + col) = make_float2(v0, v1);
                } else if (EPI == 2) {
                    v0 = gelu_exact(v0); v1 = gelu_exact(v1);
                    *(uint32_t*)(Ch + (size_t)r * N + col) = pack_hf(v0, v1);
                } else if (EPI == 3) {
                    int which = col >> 10;
                    int h = (col >> 6) & 15;
                    int e = col & 63;
                    int bb = r >> 11, s = r & 2047;
                    size_t o = (((size_t)(bb * 16 + h)) * SEQ + s) * D_HEAD + e;
                    if (which == 0) { v0 *= QSCALE; v1 *= QSCALE; }
                    hf* dst = (which == 0) ? Qd : (which == 1) ? Kd : Vd;
                    *(uint32_t*)(dst + o) = pack_hf(v0, v1);
                }
            }
        }
    }
}

// ---------------- fp16 HMMA flash attention + absorbed weight transposes ------------
// grid (16, 32 + 18): by<32 = attention; by>=32 = Wo/W1/W2 transpose tiles (filling
// the attention tail wave; outputs needed only by later GEMMs).
// smem: Q 0 (16KB); stage s at 16384 + s*16384: K 0, V 8192
#define ATT_SMEM (16384 + 2 * 16384)
#define TRB 288  // transpose blocks = 16 * 18

__global__ __launch_bounds__(256, 2) void attn_mma(
    const hf* __restrict__ q_g, const hf* __restrict__ k_g, const hf* __restrict__ v_g,
    hf* __restrict__ oh,
    const float* __restrict__ Wo, const float* __restrict__ W1, const float* __restrict__ W2,
    hf* __restrict__ dWo, hf* __restrict__ dW1, hf* __restrict__ dW2) {
    extern __shared__ char smem[];
    const int tid = threadIdx.x;

    if (blockIdx.y >= BH) {
        // ---- transpose path: 9216 32x32 tiles over 288 blocks, 32 tiles each ----
        float (*t)[33] = (float(*)[33])smem;
        const int tb = (blockIdx.y - BH) * 16 + blockIdx.x;
        const int tx = tid & 31, ty = tid >> 5;
#pragma unroll 1
        for (int it = 0; it < 32; it++) {
            int tile = tb + it * TRB;  // 0..9215
            const float* src;
            hf* dst;
            int k0, n0, srcStride, Kd;
            if (tile < 1024) {
                k0 = (tile & 31) * 32; n0 = (tile >> 5) * 32;
                src = Wo; srcStride = D_MODEL; dst = dWo; Kd = D_MODEL;
            } else if (tile < 5120) {
                int tt = tile - 1024;
                k0 = (tt & 31) * 32; n0 = (tt >> 5) * 32;
                src = W1; srcStride = D_FF; dst = dW1; Kd = D_MODEL;
            } else {
                int tt = tile - 5120;
                k0 = (tt & 127) * 32; n0 = (tt >> 7) * 32;
                src = W2; srcStride = D_MODEL; dst = dW2; Kd = D_FF;
            }
#pragma unroll
            for (int i = 0; i < 4; i++)
                t[ty + i * 8][tx] = src[(size_t)(k0 + ty + i * 8) * srcStride + n0 + tx];
            __syncthreads();
#pragma unroll
            for (int i = 0; i < 4; i++) {
                size_t o = (size_t)(n0 + ty + i * 8) * Kd + k0 + tx;
                dst[o] = __float2half_rn(t[tx][ty + i * 8]);
            }
            __syncthreads();
        }
        return;
    }

    const uint32_t sb = smem_to_u32(smem);
    const int lane = tid & 31;
    const int warp = tid >> 5;
    const int bh = blockIdx.y;
    const int q0 = blockIdx.x * 128;

    const char* qb = (const char*)(q_g + ((size_t)bh * SEQ + q0) * D_HEAD);
    const char* kb = (const char*)(k_g + (size_t)bh * SEQ * D_HEAD);
    const char* vb = (const char*)(v_g + (size_t)bh * SEQ * D_HEAD);

    {
#pragma unroll
        for (int j = 0; j < 4; j++) {
            int id = tid + j * 256;
            int row = (id >> 3) & 127, seg = id & 7;
            uint32_t dst = sb + (uint32_t)row * 128 + ((uint32_t)(seg ^ (row & 7)) << 4);
            cp_async16(dst, qb + (size_t)row * 128 + seg * 16);
        }
    }
    auto issue_kv = [&](int kt) {
        const uint32_t stg = sb + 16384 + (uint32_t)(kt & 1) * 16384;
        const size_t gof = (size_t)kt * 64 * 128;
#pragma unroll
        for (int j = 0; j < 4; j++) {
            int id = tid + j * 256;
            int arr = id >> 9, row = (id >> 3) & 63, seg = id & 7;
            const char* src = ((arr == 0) ? kb : vb) + gof + (size_t)row * 128 + seg * 16;
            uint32_t dst = stg + (uint32_t)arr * 8192 + (uint32_t)row * 128 +
                           ((uint32_t)(seg ^ (row & 7)) << 4);
            cp_async16(dst, src);
        }
    };

    issue_kv(0);
    cp_commit();
    issue_kv(1);
    cp_commit();

    float accO[8][4];
#pragma unroll
    for (int t = 0; t < 8; t++)
#pragma unroll
        for (int q = 0; q < 4; q++) accO[t][q] = 0.f;
    float m0 = -1e30f, m1 = -1e30f, l0 = 0.f, l1 = 0.f;

    uint32_t qf[4][4];
    const int qRow = warp * 16 + (lane & 15);
    const uint32_t qSw = (uint32_t)(qRow & 7);
    const uint32_t qRowB = (uint32_t)qRow * 128;

    const int NT = SEQ / 64;
    for (int kt = 0; kt < NT; kt++) {
        cp_wait<1>();
        __syncthreads();
        if (kt == 0) {
#pragma unroll
            for (int ks = 0; ks < 4; ks++) {
                uint32_t seg = ((uint32_t)(ks * 2 + (lane >> 4)) ^ qSw) << 4;
                ldm_x4(qf[ks][0], qf[ks][1], qf[ks][2], qf[ks][3], sb + qRowB + seg);
            }
        }
        const uint32_t stg = sb + 16384 + (uint32_t)(kt & 1) * 16384;

        // ---- S = Q K^T (1 pass) ----
        float S[8][4];
#pragma unroll
        for (int t = 0; t < 8; t++)
#pragma unroll
            for (int q = 0; q < 4; q++) S[t][q] = 0.f;

        const int nRow = lane & 15;
        const int kh4 = lane >> 4;
#pragma unroll
        for (int ks = 0; ks < 4; ks++) {
            uint32_t kh[4][4];
#pragma unroll
            for (int g = 0; g < 4; g++) {
                int row = g * 16 + nRow;
                uint32_t seg = ((uint32_t)(ks * 2 + kh4) ^ (uint32_t)(row & 7)) << 4;
                ldm_x4(kh[g][0], kh[g][1], kh[g][2], kh[g][3],
                       stg + (uint32_t)row * 128 + seg);
            }
#pragma unroll
            for (int g = 0; g < 4; g++) {
                float* c0 = S[2 * g];
                float* c1 = S[2 * g + 1];
                mma_f16(c0[0], c0[1], c0[2], c0[3],
                        qf[ks][0], qf[ks][1], qf[ks][2], qf[ks][3], kh[g][0], kh[g][2]);
                mma_f16(c1[0], c1[1], c1[2], c1[3],
                        qf[ks][0], qf[ks][1], qf[ks][2], qf[ks][3], kh[g][1], kh[g][3]);
            }
        }

        // ---- online softmax (f32x2 packed exp2, base-2 domain) ----
        float mx0 = S[0][0], mx1 = S[0][2];
#pragma unroll
        for (int t = 0; t < 8; t++) {
            mx0 = fmaxf(mx0, fmaxf(S[t][0], S[t][1]));
            mx1 = fmaxf(mx1, fmaxf(S[t][2], S[t][3]));
        }
        mx0 = fmaxf(mx0, __shfl_xor_sync(0xffffffffu, mx0, 1));
        mx0 = fmaxf(mx0, __shfl_xor_sync(0xffffffffu, mx0, 2));
        mx1 = fmaxf(mx1, __shfl_xor_sync(0xffffffffu, mx1, 1));
        mx1 = fmaxf(mx1, __shfl_xor_sync(0xffffffffu, mx1, 2));
        float mn0 = fmaxf(m0, mx0), mn1 = fmaxf(m1, mx1);
        float cr0 = m0 - mn0, cr1 = m1 - mn1;
        exp2_pair(cr0, cr1);
        m0 = mn0; m1 = mn1;
        float sum0 = 0.f, sum1 = 0.f;
#pragma unroll
        for (int t = 0; t < 8; t++) {
            float a0 = S[t][0] - mn0, a1 = S[t][1] - mn0;
            float b0 = S[t][2] - mn1, b1 = S[t][3] - mn1;
            exp2_pair(a0, a1);
            exp2_pair(b0, b1);
            S[t][0] = a0; S[t][1] = a1; S[t][2] = b0; S[t][3] = b1;
            sum0 += a0 + a1;
            sum1 += b0 + b1;
        }
        sum0 += __shfl_xor_sync(0xffffffffu, sum0, 1);
        sum0 += __shfl_xor_sync(0xffffffffu, sum0, 2);
        sum1 += __shfl_xor_sync(0xffffffffu, sum1, 1);
        sum1 += __shfl_xor_sync(0xffffffffu, sum1, 2);
        l0 = l0 * cr0 + sum0;
        l1 = l1 * cr1 + sum1;
#pragma unroll
        for (int t = 0; t < 8; t++) {
            accO[t][0] *= cr0; accO[t][1] *= cr0;
            accO[t][2] *= cr1; accO[t][3] *= cr1;
        }

        // ---- O += P V (1 pass) ----
        const int vRow16 = lane & 15;
        const int vEh = lane >> 4;
#pragma unroll
        for (int ks = 0; ks < 4; ks++) {
            uint32_t pa[4];
            pa[0] = pack_hf(S[2 * ks][0], S[2 * ks][1]);
            pa[1] = pack_hf(S[2 * ks][2], S[2 * ks][3]);
            pa[2] = pack_hf(S[2 * ks + 1][0], S[2 * ks + 1][1]);
            pa[3] = pack_hf(S[2 * ks + 1][2], S[2 * ks + 1][3]);

            uint32_t vh[4][4];
#pragma unroll
            for (int g = 0; g < 4; g++) {
                int row = ks * 16 + vRow16;
                uint32_t seg = ((uint32_t)(g * 2 + vEh) ^ (uint32_t)(row & 7)) << 4;
                ldm_x4_t(vh[g][0], vh[g][1], vh[g][2], vh[g][3],
                         stg + 8192 + (uint32_t)row * 128 + seg);
            }
#pragma unroll
            for (int g = 0; g < 4; g++) {
                float* c0 = accO[2 * g];
                float* c1 = accO[2 * g + 1];
                mma_f16(c0[0], c0[1], c0[2], c0[3],
                        pa[0], pa[1], pa[2], pa[3], vh[g][0], vh[g][1]);
                mma_f16(c1[0], c1[1], c1[2], c1[3],
                        pa[0], pa[1], pa[2], pa[3], vh[g][2], vh[g][3]);
            }
        }
        __syncthreads();
        if (kt + 2 < NT) issue_kv(kt + 2);
        cp_commit();
    }

    // ---- epilogue ----
    float inv0 = 1.0f / l0, inv1 = 1.0f / l1;
    const int b = bh >> 4, h = bh & 15;
    const int r1 = q0 + warp * 16 + (lane >> 2);
    const int r2 = r1 + 8;
    size_t t1 = ((size_t)(b * SEQ) + r1) * D_MODEL + h * D_HEAD;
    size_t t2 = ((size_t)(b * SEQ) + r2) * D_MODEL + h * D_HEAD;
#pragma unroll
    for (int t = 0; t < 8; t++) {
        int e = t * 8 + (lane & 3) * 2;
        *(uint32_t*)(oh + t1 + e) = pack_hf(accO[t][0] * inv0, accO[t][1] * inv0);
        *(uint32_t*)(oh + t2 + e) = pack_hf(accO[t][2] * inv1, accO[t][3] * inv1);
    }
}

// ---------------- launch ----------------
extern "C" void kernel_launch(void* const* d_in, const int* in_sizes, int n_in,
                              void* d_out, int out_size) {
    const float* x    = (const float*)d_in[0];
    const float* Wq   = (const float*)d_in[1];
    const float* Wk   = (const float*)d_in[2];
    const float* Wv   = (const float*)d_in[3];
    const float* Wo   = (const float*)d_in[4];
    const float* bo   = (const float*)d_in[5];
    const float* ln1g = (const float*)d_in[6];
    const float* ln1b = (const float*)d_in[7];
    const float* ln2g = (const float*)d_in[8];
    const float* ln2b = (const float*)d_in[9];
    const float* W1   = (const float*)d_in[10];
    const float* b1   = (const float*)d_in[11];
    const float* W2   = (const float*)d_in[12];
    const float* b2   = (const float*)d_in[13];
    float* out = (float*)d_out;

    hf *pWqkv, *pWo, *pW1, *pW2, *pXn, *pAt, *pHn, *pFf, *pQ, *pK, *pV;
    float* pHid;
    cudaGetSymbolAddress((void**)&pWqkv, g_WqkvT);
    cudaGetSymbolAddress((void**)&pWo, g_WoT);
    cudaGetSymbolAddress((void**)&pW1, g_W1T);
    cudaGetSymbolAddress((void**)&pW2, g_W2T);
    cudaGetSymbolAddress((void**)&pXn, g_xn);
    cudaGetSymbolAddress((void**)&pAt, g_at);
    cudaGetSymbolAddress((void**)&pHn, g_hn);
    cudaGetSymbolAddress((void**)&pFf, g_ff);
    cudaGetSymbolAddress((void**)&pQ, g_q);
    cudaGetSymbolAddress((void**)&pK, g_k);
    cudaGetSymbolAddress((void**)&pV, g_v);
    cudaGetSymbolAddress((void**)&pHid, g_hidden);

    const int GEMM_SMEM = GSTAGES * STAGE_BYTES;  // 98304
    cudaFuncSetAttribute(gemm_mma<1>, cudaFuncAttributeMaxDynamicSharedMemorySize, GEMM_SMEM);
    cudaFuncSetAttribute(gemm_mma<2>, cudaFuncAttributeMaxDynamicSharedMemorySize, GEMM_SMEM);
    cudaFuncSetAttribute(gemm_mma<3>, cudaFuncAttributeMaxDynamicSharedMemorySize, GEMM_SMEM);
    cudaFuncSetAttribute(attn_mma, cudaFuncAttributeMaxDynamicSharedMemorySize, ATT_SMEM);

    // prep: Wqkv transpose + LN1 only
    prep_k<<<7168, 256>>>(Wq, Wk, Wv, x, ln1g, ln1b, pWqkv, pXn);
    // QKV projection (1-pass) -> head-major fp16 q(scaled)/k/v
    gemm_mma<3><<<dim3(QKV_N / 128, TOKENS / 128), 256, GEMM_SMEM>>>(
        pXn, pWqkv, D_MODEL, QKV_N, nullptr, nullptr, nullptr, nullptr, pQ, pK, pV);
    // flash attention + absorbed Wo/W1/W2 transposes in tail blocks
    attn_mma<<<dim3(SEQ / 128, BH + 18), 256, ATT_SMEM>>>(
        pQ, pK, pV, pAt, Wo, W1, W2, pWo, pW1, pW2);
    // O projection (unsplit) + bias + residual
    gemm_mma<1><<<dim3(D_MODEL / 128, TOKENS / 128), 256, GEMM_SMEM>>>(
        pAt, pWo, D_MODEL, D_MODEL, pHid, nullptr, bo, x, nullptr, nullptr, nullptr);
    layernorm_k<<<TOKENS, 256>>>(pHid, ln2g, ln2b, pHn);
    // FF1 (1-pass) + bias + GELU
    gemm_mma<2><<<dim3(D_FF / 128, TOKENS / 128), 256, GEMM_SMEM>>>(
        pHn, pW1, D_MODEL, D_FF, nullptr, pFf, b1, nullptr, nullptr, nullptr, nullptr);
    // FF2 (1-pass) + bias + residual -> out
    gemm_mma<1><<<dim3(D_MODEL / 128, TOKENS / 128), 256, GEMM_SMEM>>>(
        pFf, pW2, D_FF, D_MODEL, out, nullptr, b2, pHid, nullptr, nullptr, nullptr);
}